// round 13
// baseline (speedup 1.0000x reference)
#include <cuda_runtime.h>
#include <cuda_bf16.h>
#include <math.h>

#define BB 64
#define SS 64
#define WW 12
#define SYM 128
#define HID 256
#define EE 64
#define RR 32
#define VV 32000

typedef unsigned long long u64;

__device__ __align__(16) float g_sent[BB*SS*SYM];
__device__ __align__(16) float g_qsum[BB*SYM];
__device__ __align__(16) float g_e1[BB*SS*EE];
__device__ __align__(16) float g_e2[BB*SS*EE];
__device__ __align__(16) float g_r1[BB*SS*RR];
__device__ __align__(16) float g_r2[BB*SS*RR];
__device__ __align__(16) float g_r3[BB*SS*RR];
__device__ __align__(16) float g_qe1[BB*EE];
__device__ __align__(16) float g_qe2[BB*EE];
__device__ __align__(16) float g_qr1[BB*RR];
__device__ __align__(16) float g_qr2[BB*RR];
__device__ __align__(16) float g_qr3[BB*RR];
__device__ __align__(16) float g_gram[(size_t)BB*9*SS*SS];
__device__ __align__(16) float g_abc[(size_t)BB*3*SS*EE];
__device__ __align__(16) float g_isum[BB*EE];

__device__ __forceinline__ u64 fma2(u64 a, u64 b, u64 c) {
    u64 d;
    asm("fma.rn.f32x2 %0, %1, %2, %3;" : "=l"(d) : "l"(a), "l"(b), "l"(c));
    return d;
}
__device__ __forceinline__ float2 unpack2(u64 a) {
    float2 r;
    asm("mov.b64 {%0,%1}, %2;" : "=f"(r.x), "=f"(r.y) : "l"(a));
    return r;
}
__device__ __forceinline__ u64 pack2(float x, float y) {
    u64 r;
    asm("mov.b64 %0, {%1,%2};" : "=l"(r) : "f"(x), "f"(y));
    return r;
}
// fast tanh via MUFU ex2/rcp: rel err ~1e-7, handles +-inf saturation correctly
__device__ __forceinline__ float fast_tanh(float x) {
    float e = __expf(2.f * x);
    return 1.f - __fdividef(2.f, e + 1.f);
}

// ---------------- 1) embedding ----------------
__global__ void embed_kernel(const int* __restrict__ story, const int* __restrict__ query,
                             const float* __restrict__ WE, const float* __restrict__ PE) {
    int r = blockIdx.x;
    int e = threadIdx.x;
    const int* idx;
    float* dst;
    if (r < BB*SS) { idx = story + r*WW; dst = g_sent + r*SYM; }
    else           { int rb = r - BB*SS; idx = query + rb*WW; dst = g_qsum + rb*SYM; }
    float acc = 0.f;
#pragma unroll
    for (int w = 0; w < WW; ++w) {
        int t = __ldg(idx + w);
        acc = fmaf(WE[(size_t)t*SYM + e], PE[w*SYM + e], acc);
    }
    dst[e] = acc;
}

// ---------------- 2) fused 5-head MLP, double-buffered staging ----------------
#define XSTR 132
#define W1S 260
#define W1CH (16*W1S)              /* 4160 floats per W1 buffer */
#define W2S64 68
#define W2S32 36
#define HSTR 260
#define MLP_SMEM_FLOATS (32*XSTR + 2*W1CH + 32*HSTR)   /* 20864 floats = 83.5KB */
__global__ void __launch_bounds__(128) mlp5_kernel(
    const float* __restrict__ Xs_story, const float* __restrict__ Xs_query,
    const float* __restrict__ ueW1, const float* __restrict__ ueb1,
    const float* __restrict__ ueW2, const float* __restrict__ ueb2,
    const float* __restrict__ urW1, const float* __restrict__ urb1,
    const float* __restrict__ urW2, const float* __restrict__ urb2,
    const float* __restrict__ ieW1, const float* __restrict__ ieb1,
    const float* __restrict__ ieW2, const float* __restrict__ ieb2,
    const float* __restrict__ irW1, const float* __restrict__ irb1,
    const float* __restrict__ irW2, const float* __restrict__ irb2,
    float* __restrict__ so0, float* __restrict__ so1,
    float* __restrict__ so2, float* __restrict__ so3, float* __restrict__ so4,
    float* __restrict__ qo0, float* __restrict__ qo1,
    float* __restrict__ qo2, float* __restrict__ qo3, float* __restrict__ qo4)
{
    extern __shared__ float smm[];
    float* Xs = smm;                 // 32 x 132
    float* Ws = Xs + 32*XSTR;        // 2 x 4160 (layer1 ping-pong); layer2 reuses buffer 0 region
    float* Hs = Ws + 2*W1CH;         // 32 x 260

    int h = blockIdx.y;
    bool is_q = (blockIdx.x >= BB*SS/32);
    const float* X = is_q ? Xs_query : Xs_story;
    int row0 = (is_q ? (blockIdx.x - BB*SS/32) : blockIdx.x) * 32;

    const float *eW1 = is_q ? ieW1 : ueW1, *eb1 = is_q ? ieb1 : ueb1;
    const float *eW2 = is_q ? ieW2 : ueW2, *eb2 = is_q ? ieb2 : ueb2;
    const float *rW1 = is_q ? irW1 : urW1, *rb1 = is_q ? irb1 : urb1;
    const float *rW2 = is_q ? irW2 : urW2, *rb2 = is_q ? irb2 : urb2;

    const float *W1, *b1, *W2, *b2;
    float* out;
    int Dout;
    if (h < 2) {
        W1 = eW1 + (size_t)h*SYM*HID; b1 = eb1 + h*HID;
        W2 = eW2 + (size_t)h*HID*EE;  b2 = eb2 + h*EE;
        out = h ? (is_q ? qo1 : so1) : (is_q ? qo0 : so0); Dout = EE;
    } else {
        int g = h - 2;
        W1 = rW1 + (size_t)g*SYM*HID; b1 = rb1 + g*HID;
        W2 = rW2 + (size_t)g*HID*RR;  b2 = rb2 + g*RR;
        out = (g == 0) ? (is_q ? qo2 : so2)
            : ((g == 1) ? (is_q ? qo3 : so3) : (is_q ? qo4 : so4));
        Dout = RR;
    }

    int tid = threadIdx.x;
    int ty = tid >> 4, tx = tid & 15;

    for (int idx = tid; idx < 32*32; idx += 128) {
        int r = idx >> 5, c4 = idx & 31;
        ((float4*)(Xs + r*XSTR))[c4] = ((const float4*)(X + (size_t)(row0 + r)*SYM))[c4];
    }

    // ---- layer 1, ping-pong W staging ----
    u64 acc2[4][8];
    {
        const u64* bp = (const u64*)(b1 + tx*16);
#pragma unroll
        for (int c = 0; c < 8; ++c) {
            u64 bv = bp[c];
#pragma unroll
            for (int r = 0; r < 4; ++r) acc2[r][c] = bv;
        }
    }

    float4 wreg[8];
    // prefetch chunk 0
    {
        const float4* src = (const float4*)W1;
#pragma unroll
        for (int i = 0; i < 8; ++i) wreg[i] = src[i*128 + tid];
    }
    // store chunk 0 to buffer 0
#pragma unroll
    for (int i = 0; i < 8; ++i) {
        int id = i*128 + tid;
        int r = id >> 6, c4 = id & 63;
        ((float4*)(Ws + r*W1S))[c4] = wreg[i];
    }
    __syncthreads();

    for (int kk = 0; kk < 8; ++kk) {
        if (kk < 7) {
            const float4* src = (const float4*)(W1 + (size_t)(kk+1)*16*HID);
#pragma unroll
            for (int i = 0; i < 8; ++i) wreg[i] = src[i*128 + tid];
        }
        const float* Wc = Ws + (kk & 1)*W1CH;
#pragma unroll
        for (int k2 = 0; k2 < 8; ++k2) {
            u64 xx0[4], xx1[4];
#pragma unroll
            for (int r = 0; r < 4; ++r) {
                u64 xu = *(const u64*)(Xs + (ty*4 + r)*XSTR + kk*16 + k2*2);
                float2 xf = unpack2(xu);
                xx0[r] = pack2(xf.x, xf.x);
                xx1[r] = pack2(xf.y, xf.y);
            }
            const ulonglong2* w0p = (const ulonglong2*)(Wc + (k2*2    )*W1S + tx*16);
            const ulonglong2* w1p = (const ulonglong2*)(Wc + (k2*2 + 1)*W1S + tx*16);
#pragma unroll
            for (int q = 0; q < 4; ++q) {
                ulonglong2 w0 = w0p[q];
                ulonglong2 w1 = w1p[q];
#pragma unroll
                for (int r = 0; r < 4; ++r) {
                    acc2[r][2*q  ] = fma2(xx0[r], w0.x, acc2[r][2*q  ]);
                    acc2[r][2*q+1] = fma2(xx0[r], w0.y, acc2[r][2*q+1]);
                    acc2[r][2*q  ] = fma2(xx1[r], w1.x, acc2[r][2*q  ]);
                    acc2[r][2*q+1] = fma2(xx1[r], w1.y, acc2[r][2*q+1]);
                }
            }
        }
        if (kk < 7) {
            float* dstb = Ws + ((kk+1) & 1)*W1CH;
#pragma unroll
            for (int i = 0; i < 8; ++i) {
                int id = i*128 + tid;
                int r = id >> 6, c4 = id & 63;
                ((float4*)(dstb + r*W1S))[c4] = wreg[i];
            }
        }
        __syncthreads();
    }

    // tanh -> Hs (fast tanh)
#pragma unroll
    for (int r = 0; r < 4; ++r)
#pragma unroll
        for (int c = 0; c < 8; ++c) {
            float2 v = unpack2(acc2[r][c]);
            *(u64*)(Hs + (ty*4 + r)*HSTR + tx*16 + 2*c) = pack2(fast_tanh(v.x), fast_tanh(v.y));
        }
    __syncthreads();

    // ---- layer 2: reg-prefetch, single buffer (in Ws region) ----
    if (Dout == EE) {
        const int st = W2S64;
        u64 oa[4][2];
        {
            const u64* bp = (const u64*)(b2 + tx*4);
            u64 b0 = bp[0], b1v = bp[1];
#pragma unroll
            for (int r = 0; r < 4; ++r) { oa[r][0] = b0; oa[r][1] = b1v; }
        }
        float4 w2reg[8];
        {
            const float4* src = (const float4*)W2;
#pragma unroll
            for (int i = 0; i < 8; ++i) w2reg[i] = src[i*128 + tid];
        }
#pragma unroll
        for (int i = 0; i < 8; ++i) {
            int id = i*128 + tid;
            int r = id >> 4, c4 = id & 15;
            ((float4*)(Ws + r*st))[c4] = w2reg[i];
        }
        __syncthreads();
        for (int kk = 0; kk < 4; ++kk) {
            if (kk < 3) {
                const float4* src = (const float4*)(W2 + (size_t)(kk+1)*64*EE);
#pragma unroll
                for (int i = 0; i < 8; ++i) w2reg[i] = src[i*128 + tid];
            }
#pragma unroll
            for (int k2 = 0; k2 < 32; ++k2) {
                u64 hh0[4], hh1[4];
#pragma unroll
                for (int r = 0; r < 4; ++r) {
                    u64 hu = *(const u64*)(Hs + (ty*4 + r)*HSTR + kk*64 + k2*2);
                    float2 hf = unpack2(hu);
                    hh0[r] = pack2(hf.x, hf.x);
                    hh1[r] = pack2(hf.y, hf.y);
                }
                const u64* w0p = (const u64*)(Ws + (k2*2    )*st + tx*4);
                const u64* w1p = (const u64*)(Ws + (k2*2 + 1)*st + tx*4);
                u64 w00 = w0p[0], w01 = w0p[1], w10 = w1p[0], w11 = w1p[1];
#pragma unroll
                for (int r = 0; r < 4; ++r) {
                    oa[r][0] = fma2(hh0[r], w00, oa[r][0]);
                    oa[r][1] = fma2(hh0[r], w01, oa[r][1]);
                    oa[r][0] = fma2(hh1[r], w10, oa[r][0]);
                    oa[r][1] = fma2(hh1[r], w11, oa[r][1]);
                }
            }
            __syncthreads();
            if (kk < 3) {
#pragma unroll
                for (int i = 0; i < 8; ++i) {
                    int id = i*128 + tid;
                    int r = id >> 4, c4 = id & 15;
                    ((float4*)(Ws + r*st))[c4] = w2reg[i];
                }
                __syncthreads();
            }
        }
#pragma unroll
        for (int r = 0; r < 4; ++r) {
            *(u64*)(out + (size_t)(row0 + ty*4 + r)*EE + tx*4    ) = oa[r][0];
            *(u64*)(out + (size_t)(row0 + ty*4 + r)*EE + tx*4 + 2) = oa[r][1];
        }
    } else {
        const int st = W2S32;
        u64 oa[4];
        {
            u64 b0 = *(const u64*)(b2 + tx*2);
#pragma unroll
            for (int r = 0; r < 4; ++r) oa[r] = b0;
        }
        float4 w2reg[4];
        {
            const float4* src = (const float4*)W2;
#pragma unroll
            for (int i = 0; i < 4; ++i) w2reg[i] = src[i*128 + tid];
        }
#pragma unroll
        for (int i = 0; i < 4; ++i) {
            int id = i*128 + tid;
            int r = id >> 3, c4 = id & 7;
            ((float4*)(Ws + r*st))[c4] = w2reg[i];
        }
        __syncthreads();
        for (int kk = 0; kk < 4; ++kk) {
            if (kk < 3) {
                const float4* src = (const float4*)(W2 + (size_t)(kk+1)*64*RR);
#pragma unroll
                for (int i = 0; i < 4; ++i) w2reg[i] = src[i*128 + tid];
            }
#pragma unroll
            for (int k2 = 0; k2 < 32; ++k2) {
                u64 hh0[4], hh1[4];
#pragma unroll
                for (int r = 0; r < 4; ++r) {
                    u64 hu = *(const u64*)(Hs + (ty*4 + r)*HSTR + kk*64 + k2*2);
                    float2 hf = unpack2(hu);
                    hh0[r] = pack2(hf.x, hf.x);
                    hh1[r] = pack2(hf.y, hf.y);
                }
                u64 w0 = *(const u64*)(Ws + (k2*2    )*st + tx*2);
                u64 w1 = *(const u64*)(Ws + (k2*2 + 1)*st + tx*2);
#pragma unroll
                for (int r = 0; r < 4; ++r) {
                    oa[r] = fma2(hh0[r], w0, oa[r]);
                    oa[r] = fma2(hh1[r], w1, oa[r]);
                }
            }
            __syncthreads();
            if (kk < 3) {
#pragma unroll
                for (int i = 0; i < 4; ++i) {
                    int id = i*128 + tid;
                    int r = id >> 3, c4 = id & 7;
                    ((float4*)(Ws + r*st))[c4] = w2reg[i];
                }
                __syncthreads();
            }
        }
#pragma unroll
        for (int r = 0; r < 4; ++r)
            *(u64*)(out + (size_t)(row0 + ty*4 + r)*RR + tx*2) = oa[r];
    }
}

// ---------------- 3a) Gram kernel (register-tiled, f32x2) ----------------
__global__ void __launch_bounds__(128) gram_kernel() {
    __shared__ float sX[64*66];
    __shared__ float sY[64*66];
    int b = blockIdx.x, w = blockIdx.y, tid = threadIdx.x;
    size_t off64 = (size_t)b*SS*EE;
    size_t off32 = (size_t)b*SS*RR;
    const float *X, *Y;
    int D, dsh;
    if (w == 0)      { X = g_e1 + off64; Y = g_e1 + off64; D = 64; dsh = 6; }
    else if (w == 1) { X = g_e1 + off64; Y = g_e2 + off64; D = 64; dsh = 6; }
    else if (w == 2) { X = g_e2 + off64; Y = g_e2 + off64; D = 64; dsh = 6; }
    else {
        int pq = w - 3;
        const float* rb[3] = { g_r1 + off32, g_r2 + off32, g_r3 + off32 };
        const int pi[6] = {0,0,0,1,1,2};
        const int qi[6] = {0,1,2,1,2,2};
        X = rb[pi[pq]]; Y = rb[qi[pq]]; D = 32; dsh = 5;
    }
    for (int idx = tid; idx < 64*D; idx += 128) {
        int row = idx >> dsh, d = idx & (D-1);
        sX[row*66 + d] = X[idx];
        sY[row*66 + d] = Y[idx];
    }
    __syncthreads();

    int ty = tid >> 3, tx = tid & 7;
    int s0 = ty * 4, t0 = tx * 8;
    u64 acc[4][8];
#pragma unroll
    for (int i = 0; i < 4; ++i)
#pragma unroll
        for (int j = 0; j < 8; ++j) acc[i][j] = 0ull;

    int DP = D >> 1;
#pragma unroll 4
    for (int dp = 0; dp < DP; ++dp) {
        u64 x2[4], y2[8];
#pragma unroll
        for (int i = 0; i < 4; ++i) x2[i] = *(const u64*)(sX + (s0+i)*66 + 2*dp);
#pragma unroll
        for (int j = 0; j < 8; ++j) y2[j] = *(const u64*)(sY + (t0+j)*66 + 2*dp);
#pragma unroll
        for (int i = 0; i < 4; ++i)
#pragma unroll
            for (int j = 0; j < 8; ++j)
                acc[i][j] = fma2(x2[i], y2[j], acc[i][j]);
    }

    float* out = g_gram + ((size_t)(b*9 + w) << 12);
#pragma unroll
    for (int i = 0; i < 4; ++i)
#pragma unroll
        for (int j = 0; j < 8; ++j) {
            float2 p = unpack2(acc[i][j]);
            out[(s0+i)*64 + (t0+j)] = p.x + p.y;
        }
}

// ---------------- 3b) Gram-space scan, paired steps: grid (BB, 2), block 256 ----------------
#define SL_SMEM_FLOATS (9*4096 + 5*2048 + 1536)
__global__ void __launch_bounds__(256) scanloop_kernel() {
    extern __shared__ float sm[];
    float* sCoef = sm;
    float* sAh   = sm + 9*4096;
    float* sBh   = sAh + 2048;
    float* sCh   = sBh + 2048;
    float* sE1h  = sCh + 2048;
    float* sE2h  = sE1h + 2048;
    float* sP    = sE2h + 2048;   // 6 x 256

    int b = blockIdx.x, by = blockIdx.y, tid = threadIdx.x;
    int g = tid >> 5, fl = tid & 31;

    {
        const float* G = g_gram + (size_t)b*9*4096;
        for (int i = tid; i < 4096; i += 256) {
            int s = i >> 6, t = i & 63;
            int ts = (t << 6) + s;
            float ge11  = G[i];
            float ge12  = G[4096 + i];
            float ge12t = G[4096 + ts];
            float ge22  = G[2*4096 + i];
            float gr11  = G[3*4096 + i];
            float gr12  = G[4*4096 + i];
            float gr12t = G[4*4096 + ts];
            float gr13  = G[5*4096 + i];
            float gr13t = G[5*4096 + ts];
            float gr22  = G[6*4096 + i];
            float gr23  = G[7*4096 + i];
            float gr23t = G[7*4096 + ts];
            float gr33  = G[8*4096 + i];
            sCoef[          i] = ge11  * gr11;
            sCoef[  4096 +  i] = ge11  * gr12;
            sCoef[2*4096 +  i] = ge12  * gr13;
            sCoef[3*4096 +  i] = ge11  * gr12t;
            sCoef[4*4096 +  i] = ge11  * gr22;
            sCoef[5*4096 +  i] = ge12  * gr23;
            sCoef[6*4096 +  i] = ge12t * gr13t;
            sCoef[7*4096 +  i] = ge12t * gr23t;
            sCoef[8*4096 +  i] = ge22  * gr33;
        }
        for (int i = tid; i < 2048; i += 256) {
            int t = i >> 5, f2 = i & 31;
            sE1h[i] = g_e1[((size_t)(b*SS + t))*EE + (by << 5) + f2];
            sE2h[i] = g_e2[((size_t)(b*SS + t))*EE + (by << 5) + f2];
        }
    }
    __syncthreads();

    for (int s = 0; s < SS; s += 2) {
        int row0 = s << 6, row1 = (s + 1) << 6;
        float wa0=0.f, wb0=0.f, wc0=0.f, ma0=0.f, mb0=0.f, mc0=0.f, ba0=0.f, bb0=0.f, bc0=0.f;
        float wa1=0.f, wb1=0.f, wc1=0.f, ma1=0.f, mb1=0.f, mc1=0.f, ba1=0.f, bb1=0.f, bc1=0.f;
        for (int t = g; t < s; t += 8) {
            int tf = (t << 5) + fl;
            float at = sAh[tf], bt = sBh[tf], ct = sCh[tf];
            int s0t = row0 + t, s1t = row1 + t;
            wa0 = fmaf(sCoef[          s0t], at, wa0);
            wb0 = fmaf(sCoef[  4096 + s0t], bt, wb0);
            wc0 = fmaf(sCoef[2*4096 + s0t], ct, wc0);
            ma0 = fmaf(sCoef[3*4096 + s0t], at, ma0);
            mb0 = fmaf(sCoef[4*4096 + s0t], bt, mb0);
            mc0 = fmaf(sCoef[5*4096 + s0t], ct, mc0);
            ba0 = fmaf(sCoef[6*4096 + s0t], at, ba0);
            bb0 = fmaf(sCoef[7*4096 + s0t], bt, bb0);
            bc0 = fmaf(sCoef[8*4096 + s0t], ct, bc0);
            wa1 = fmaf(sCoef[          s1t], at, wa1);
            wb1 = fmaf(sCoef[  4096 + s1t], bt, wb1);
            wc1 = fmaf(sCoef[2*4096 + s1t], ct, wc1);
            ma1 = fmaf(sCoef[3*4096 + s1t], at, ma1);
            mb1 = fmaf(sCoef[4*4096 + s1t], bt, mb1);
            mc1 = fmaf(sCoef[5*4096 + s1t], ct, mc1);
            ba1 = fmaf(sCoef[6*4096 + s1t], at, ba1);
            bb1 = fmaf(sCoef[7*4096 + s1t], bt, bb1);
            bc1 = fmaf(sCoef[8*4096 + s1t], ct, bc1);
        }
        int pi = (g << 5) + fl;
        sP[         pi] = (wa0 + wb0) + wc0;
        sP[  256 +  pi] = (ma0 + mb0) + mc0;
        sP[2*256 +  pi] = (ba0 + bb0) + bc0;
        sP[3*256 +  pi] = (wa1 + wb1) + wc1;
        sP[4*256 +  pi] = (ma1 + mb1) + mc1;
        sP[5*256 +  pi] = (ba1 + bb1) + bc1;
        __syncthreads();
        if (tid < 32) {
            float w0 = 0.f, m0 = 0.f, bh0 = 0.f, w1 = 0.f, m1 = 0.f, bh1 = 0.f;
#pragma unroll
            for (int q = 0; q < 8; ++q) {
                int qi = (q << 5) + tid;
                w0  += sP[         qi];
                m0  += sP[  256 +  qi];
                bh0 += sP[2*256 +  qi];
                w1  += sP[3*256 +  qi];
                m1  += sP[4*256 +  qi];
                bh1 += sP[5*256 +  qi];
            }
            int rw0 = (s << 5) + tid;
            int rw1 = rw0 + 32;
            float a0 = sE2h[rw0] - w0;
            float b0 = w0 - m0;
            float c0 = sE1h[rw0] - bh0;
            sAh[rw0] = a0; sBh[rw0] = b0; sCh[rw0] = c0;
            int st = row1 + s;
            w1  += sCoef[          st]*a0 + sCoef[  4096 + st]*b0 + sCoef[2*4096 + st]*c0;
            m1  += sCoef[3*4096 + st]*a0 + sCoef[4*4096 + st]*b0 + sCoef[5*4096 + st]*c0;
            bh1 += sCoef[6*4096 + st]*a0 + sCoef[7*4096 + st]*b0 + sCoef[8*4096 + st]*c0;
            sAh[rw1] = sE2h[rw1] - w1;
            sBh[rw1] = w1 - m1;
            sCh[rw1] = sE1h[rw1] - bh1;
        }
        __syncthreads();
    }

    for (int i = tid; i < 2048; i += 256) {
        int t = i >> 5, f2 = i & 31;
        size_t base = ((size_t)(b*3)*SS + t)*EE + (by << 5) + f2;
        g_abc[base          ] = sAh[i];
        g_abc[base + SS*EE  ] = sBh[i];
        g_abc[base + 2*SS*EE] = sCh[i];
    }
}

// ---------------- 4) inference chain ----------------
#define IF_SMEM_FLOATS (3*4096 + 2*65*64 + 6*64 + 4 + 128)
__global__ void __launch_bounds__(128) infer_kernel(
    const float* __restrict__ qe1,
    const float* __restrict__ qr1, const float* __restrict__ qr2, const float* __restrict__ qr3,
    const float* __restrict__ ln_g, const float* __restrict__ ln_b)
{
    extern __shared__ float sm[];
    float* sA   = sm;
    float* sB   = sA + 4096;
    float* sC   = sB + 4096;
    float* sE1T = sC + 4096;
    float* sE2T = sE1T + 65*64;
    float* cur  = sE2T + 65*64;
    float* d1   = cur + 64;
    float* d2   = d1 + 64;
    float* ca   = d2 + 64;
    float* cb   = ca + 64;
    float* cc   = cb + 64;
    float* lnr  = cc + 64;
    float* sPar = lnr + 4;

    int b = blockIdx.x, tid = threadIdx.x;
    int g = tid >> 6, f = tid & 63;

    {
        const float4* a4 = (const float4*)(g_abc + (size_t)(b*3)*SS*EE);
        float4* s4 = (float4*)sA;
        for (int i = tid; i < 3*1024; i += 128) s4[i] = a4[i];
        for (int i = tid; i < 4096; i += 128) {
            int tt = i >> 6, ff = i & 63;
            sE1T[ff*65 + tt] = g_e1[((size_t)(b*SS + tt))*EE + ff];
            sE2T[ff*65 + tt] = g_e2[((size_t)(b*SS + tt))*EE + ff];
        }
    }
    if (tid < 64) cur[tid] = qe1[b*EE + tid];
    __syncthreads();

    float isum = 0.f;
    for (int p = 0; p < 3; ++p) {
        const float* qrp = (p == 0 ? qr1 : (p == 1 ? qr2 : qr3)) + b*RR;
        if (tid < 64) {
            int t = tid;
            float s1 = 0.f, s2 = 0.f;
            for (int f2 = 0; f2 < 64; ++f2) {
                float cv = cur[f2];
                s1 = fmaf(cv, sE1T[f2*65 + t], s1);
                s2 = fmaf(cv, sE2T[f2*65 + t], s2);
            }
            d1[t] = s1; d2[t] = s2;
        } else {
            int t = tid - 64;
            const float* r1p = g_r1 + ((size_t)(b*SS + t))*RR;
            const float* r2p = g_r2 + ((size_t)(b*SS + t))*RR;
            const float* r3p = g_r3 + ((size_t)(b*SS + t))*RR;
            float a1 = 0.f, a2 = 0.f, a3 = 0.f;
            for (int r = 0; r < RR; ++r) {
                float q = qrp[r];
                a1 = fmaf(q, r1p[r], a1);
                a2 = fmaf(q, r2p[r], a2);
                a3 = fmaf(q, r3p[r], a3);
            }
            ca[t] = a1; cb[t] = a2; cc[t] = a3;
        }
        __syncthreads();
        if (tid < 64) {
            int t = tid;
            ca[t] *= d1[t];
            cb[t] *= d1[t];
            cc[t] *= d2[t];
        }
        __syncthreads();
        {
            float acc = 0.f;
            for (int t = g; t < 64; t += 2) {
                int tf = (t << 6) + f;
                acc = fmaf(ca[t], sA[tf], fmaf(cb[t], sB[tf], fmaf(cc[t], sC[tf], acc)));
            }
            sPar[(g << 6) + f] = acc;
        }
        __syncthreads();
        if (g == 0) {
            float raw = sPar[f] + sPar[64 + f];
            float ssum = raw;
#pragma unroll
            for (int off = 16; off > 0; off >>= 1) ssum += __shfl_xor_sync(0xffffffffu, ssum, off);
            if ((f & 31) == 0) lnr[f >> 5] = ssum;
        }
        __syncthreads();
        if (g == 0) {
            float raw = sPar[f] + sPar[64 + f];
            float mean = (lnr[0] + lnr[1]) * (1.f/64.f);
            float d = raw - mean;
            float q = d * d;
#pragma unroll
            for (int off = 16; off > 0; off >>= 1) q += __shfl_xor_sync(0xffffffffu, q, off);
            if ((f & 31) == 0) lnr[2 + (f >> 5)] = q;
        }
        __syncthreads();
        if (g == 0) {
            float raw = sPar[f] + sPar[64 + f];
            float mean = (lnr[0] + lnr[1]) * (1.f/64.f);
            float var  = (lnr[2] + lnr[3]) * (1.f/64.f);
            float val = (raw - mean) * rsqrtf(var + 1e-5f) * ln_g[p*EE + f] + ln_b[p*EE + f];
            cur[f] = val;
            isum += val;
        }
        __syncthreads();
    }
    if (g == 0) g_isum[b*EE + f] = isum;
}

// ---------------- 5) output GEMM ----------------
__global__ void __launch_bounds__(128) outgemm_kernel(const float* __restrict__ Z,
                                                      float* __restrict__ out) {
    __shared__ float sI[16][64];
    int bx = blockIdx.x, by = blockIdx.y, tid = threadIdx.x;
    for (int idx = tid; idx < 1024; idx += 128)
        sI[idx >> 6][idx & 63] = g_isum[by*1024 + idx];
    __syncthreads();

    int v = bx*128 + tid;
    float acc[16];
#pragma unroll
    for (int i = 0; i < 16; ++i) acc[i] = 0.f;
#pragma unroll 4
    for (int e = 0; e < 64; ++e) {
        float z = __ldg(Z + (size_t)e*VV + v);
#pragma unroll
        for (int i = 0; i < 16; ++i)
            acc[i] = fmaf(sI[i][e], z, acc[i]);
    }
#pragma unroll
    for (int i = 0; i < 16; ++i)
        out[(size_t)(by*16 + i)*VV + v] = acc[i];
}

// ---------------- launch ----------------
extern "C" void kernel_launch(void* const* d_in, const int* in_sizes, int n_in,
                              void* d_out, int out_size) {
    const int*   story = (const int*)d_in[0];
    const int*   query = (const int*)d_in[1];
    const float* WE    = (const float*)d_in[2];
    const float* PE    = (const float*)d_in[3];
    const float* ue_W1 = (const float*)d_in[4];
    const float* ue_b1 = (const float*)d_in[5];
    const float* ue_W2 = (const float*)d_in[6];
    const float* ue_b2 = (const float*)d_in[7];
    const float* ur_W1 = (const float*)d_in[8];
    const float* ur_b1 = (const float*)d_in[9];
    const float* ur_W2 = (const float*)d_in[10];
    const float* ur_b2 = (const float*)d_in[11];
    const float* ie_W1 = (const float*)d_in[12];
    const float* ie_b1 = (const float*)d_in[13];
    const float* ie_W2 = (const float*)d_in[14];
    const float* ie_b2 = (const float*)d_in[15];
    const float* ir_W1 = (const float*)d_in[16];
    const float* ir_b1 = (const float*)d_in[17];
    const float* ir_W2 = (const float*)d_in[18];
    const float* ir_b2 = (const float*)d_in[19];
    const float* ln_g  = (const float*)d_in[20];
    const float* ln_b  = (const float*)d_in[21];
    const float* Z     = (const float*)d_in[22];
    float* out = (float*)d_out;

    const int MLP_SMEM = MLP_SMEM_FLOATS * (int)sizeof(float);
    const int SL_SMEM  = SL_SMEM_FLOATS * (int)sizeof(float);
    const int IF_SMEM  = IF_SMEM_FLOATS * (int)sizeof(float);
    cudaFuncSetAttribute(mlp5_kernel, cudaFuncAttributeMaxDynamicSharedMemorySize, MLP_SMEM);
    cudaFuncSetAttribute(scanloop_kernel, cudaFuncAttributeMaxDynamicSharedMemorySize, SL_SMEM);
    cudaFuncSetAttribute(infer_kernel, cudaFuncAttributeMaxDynamicSharedMemorySize, IF_SMEM);

    float *d_sent, *d_qsum, *d_e1, *d_e2, *d_r1, *d_r2, *d_r3;
    float *d_qe1, *d_qe2, *d_qr1, *d_qr2, *d_qr3;
    cudaGetSymbolAddress((void**)&d_sent, g_sent);
    cudaGetSymbolAddress((void**)&d_qsum, g_qsum);
    cudaGetSymbolAddress((void**)&d_e1, g_e1);
    cudaGetSymbolAddress((void**)&d_e2, g_e2);
    cudaGetSymbolAddress((void**)&d_r1, g_r1);
    cudaGetSymbolAddress((void**)&d_r2, g_r2);
    cudaGetSymbolAddress((void**)&d_r3, g_r3);
    cudaGetSymbolAddress((void**)&d_qe1, g_qe1);
    cudaGetSymbolAddress((void**)&d_qe2, g_qe2);
    cudaGetSymbolAddress((void**)&d_qr1, g_qr1);
    cudaGetSymbolAddress((void**)&d_qr2, g_qr2);
    cudaGetSymbolAddress((void**)&d_qr3, g_qr3);

    embed_kernel<<<BB*SS + BB, SYM>>>(story, query, WE, PE);

    mlp5_kernel<<<dim3(BB*SS/32 + 2, 5), 128, MLP_SMEM>>>(
        d_sent, d_qsum,
        ue_W1, ue_b1, ue_W2, ue_b2, ur_W1, ur_b1, ur_W2, ur_b2,
        ie_W1, ie_b1, ie_W2, ie_b2, ir_W1, ir_b1, ir_W2, ir_b2,
        d_e1, d_e2, d_r1, d_r2, d_r3,
        d_qe1, d_qe2, d_qr1, d_qr2, d_qr3);

    gram_kernel<<<dim3(BB, 9), 128>>>();
    scanloop_kernel<<<dim3(BB, 2), 256, SL_SMEM>>>();
    infer_kernel<<<BB, 128, IF_SMEM>>>(d_qe1, d_qr1, d_qr2, d_qr3, ln_g, ln_b);
    outgemm_kernel<<<dim3(VV/128, BB/16), 128>>>(Z, out);
}

// round 14
// speedup vs baseline: 1.0430x; 1.0430x over previous
#include <cuda_runtime.h>
#include <cuda_bf16.h>
#include <math.h>

#define BB 64
#define SS 64
#define WW 12
#define SYM 128
#define HID 256
#define EE 64
#define RR 32
#define VV 32000

typedef unsigned long long u64;

__device__ __align__(16) float g_sent[BB*SS*SYM];
__device__ __align__(16) float g_qsum[BB*SYM];
__device__ __align__(16) float g_e1[BB*SS*EE];
__device__ __align__(16) float g_e2[BB*SS*EE];
__device__ __align__(16) float g_r1[BB*SS*RR];
__device__ __align__(16) float g_r2[BB*SS*RR];
__device__ __align__(16) float g_r3[BB*SS*RR];
__device__ __align__(16) float g_qe1[BB*EE];
__device__ __align__(16) float g_qe2[BB*EE];
__device__ __align__(16) float g_qr1[BB*RR];
__device__ __align__(16) float g_qr2[BB*RR];
__device__ __align__(16) float g_qr3[BB*RR];
__device__ __align__(16) float g_gram[(size_t)BB*9*SS*SS];
__device__ __align__(16) float g_abc[(size_t)BB*3*SS*EE];
__device__ __align__(16) float g_isum[BB*EE];

__device__ __forceinline__ u64 fma2(u64 a, u64 b, u64 c) {
    u64 d;
    asm("fma.rn.f32x2 %0, %1, %2, %3;" : "=l"(d) : "l"(a), "l"(b), "l"(c));
    return d;
}
__device__ __forceinline__ float2 unpack2(u64 a) {
    float2 r;
    asm("mov.b64 {%0,%1}, %2;" : "=f"(r.x), "=f"(r.y) : "l"(a));
    return r;
}
__device__ __forceinline__ u64 pack2(float x, float y) {
    u64 r;
    asm("mov.b64 %0, {%1,%2};" : "=l"(r) : "f"(x), "f"(y));
    return r;
}
__device__ __forceinline__ float fast_tanh(float x) {
    float e = __expf(2.f * x);
    return 1.f - __fdividef(2.f, e + 1.f);
}

// ---------------- 1) embedding ----------------
__global__ void embed_kernel(const int* __restrict__ story, const int* __restrict__ query,
                             const float* __restrict__ WE, const float* __restrict__ PE) {
    int r = blockIdx.x;
    int e = threadIdx.x;
    const int* idx;
    float* dst;
    if (r < BB*SS) { idx = story + r*WW; dst = g_sent + r*SYM; }
    else           { int rb = r - BB*SS; idx = query + rb*WW; dst = g_qsum + rb*SYM; }
    float acc = 0.f;
#pragma unroll
    for (int w = 0; w < WW; ++w) {
        int t = __ldg(idx + w);
        acc = fmaf(WE[(size_t)t*SYM + e], PE[w*SYM + e], acc);
    }
    dst[e] = acc;
}

// ---------------- 2) fused 5-head MLP (R11-proven structure, fast_tanh) ----------------
#define XSTR 132
#define W1S 260
#define W2S64 68
#define W2S32 36
#define HSTR 260
#define WREG 4352
#define MLP_SMEM_FLOATS (32*XSTR + WREG + 32*HSTR)
__global__ void __launch_bounds__(128) mlp5_kernel(
    const float* __restrict__ Xs_story, const float* __restrict__ Xs_query,
    const float* __restrict__ ueW1, const float* __restrict__ ueb1,
    const float* __restrict__ ueW2, const float* __restrict__ ueb2,
    const float* __restrict__ urW1, const float* __restrict__ urb1,
    const float* __restrict__ urW2, const float* __restrict__ urb2,
    const float* __restrict__ ieW1, const float* __restrict__ ieb1,
    const float* __restrict__ ieW2, const float* __restrict__ ieb2,
    const float* __restrict__ irW1, const float* __restrict__ irb1,
    const float* __restrict__ irW2, const float* __restrict__ irb2,
    float* __restrict__ so0, float* __restrict__ so1,
    float* __restrict__ so2, float* __restrict__ so3, float* __restrict__ so4,
    float* __restrict__ qo0, float* __restrict__ qo1,
    float* __restrict__ qo2, float* __restrict__ qo3, float* __restrict__ qo4)
{
    extern __shared__ float smm[];
    float* Xs = smm;
    float* Ws = Xs + 32*XSTR;
    float* Hs = Ws + WREG;

    int h = blockIdx.y;
    bool is_q = (blockIdx.x >= BB*SS/32);
    const float* X = is_q ? Xs_query : Xs_story;
    int row0 = (is_q ? (blockIdx.x - BB*SS/32) : blockIdx.x) * 32;

    const float *eW1 = is_q ? ieW1 : ueW1, *eb1 = is_q ? ieb1 : ueb1;
    const float *eW2 = is_q ? ieW2 : ueW2, *eb2 = is_q ? ieb2 : ueb2;
    const float *rW1 = is_q ? irW1 : urW1, *rb1 = is_q ? irb1 : urb1;
    const float *rW2 = is_q ? irW2 : urW2, *rb2 = is_q ? irb2 : urb2;

    const float *W1, *b1, *W2, *b2;
    float* out;
    int Dout;
    if (h < 2) {
        W1 = eW1 + (size_t)h*SYM*HID; b1 = eb1 + h*HID;
        W2 = eW2 + (size_t)h*HID*EE;  b2 = eb2 + h*EE;
        out = h ? (is_q ? qo1 : so1) : (is_q ? qo0 : so0); Dout = EE;
    } else {
        int g = h - 2;
        W1 = rW1 + (size_t)g*SYM*HID; b1 = rb1 + g*HID;
        W2 = rW2 + (size_t)g*HID*RR;  b2 = rb2 + g*RR;
        out = (g == 0) ? (is_q ? qo2 : so2)
            : ((g == 1) ? (is_q ? qo3 : so3) : (is_q ? qo4 : so4));
        Dout = RR;
    }

    int tid = threadIdx.x;
    int ty = tid >> 4, tx = tid & 15;

    for (int idx = tid; idx < 32*32; idx += 128) {
        int r = idx >> 5, c4 = idx & 31;
        ((float4*)(Xs + r*XSTR))[c4] = ((const float4*)(X + (size_t)(row0 + r)*SYM))[c4];
    }

    u64 acc2[4][8];
    {
        const u64* bp = (const u64*)(b1 + tx*16);
#pragma unroll
        for (int c = 0; c < 8; ++c) {
            u64 bv = bp[c];
#pragma unroll
            for (int r = 0; r < 4; ++r) acc2[r][c] = bv;
        }
    }
    __syncthreads();

    for (int kk = 0; kk < 8; ++kk) {
        for (int idx = tid; idx < 16*64; idx += 128) {
            int r = idx >> 6, c4 = idx & 63;
            ((float4*)(Ws + r*W1S))[c4] = ((const float4*)(W1 + (size_t)(kk*16 + r)*HID))[c4];
        }
        __syncthreads();
#pragma unroll
        for (int k2 = 0; k2 < 8; ++k2) {
            u64 xx0[4], xx1[4];
#pragma unroll
            for (int r = 0; r < 4; ++r) {
                u64 xu = *(const u64*)(Xs + (ty*4 + r)*XSTR + kk*16 + k2*2);
                float2 xf = unpack2(xu);
                xx0[r] = pack2(xf.x, xf.x);
                xx1[r] = pack2(xf.y, xf.y);
            }
            const ulonglong2* w0p = (const ulonglong2*)(Ws + (k2*2    )*W1S + tx*16);
            const ulonglong2* w1p = (const ulonglong2*)(Ws + (k2*2 + 1)*W1S + tx*16);
#pragma unroll
            for (int q = 0; q < 4; ++q) {
                ulonglong2 w0 = w0p[q];
                ulonglong2 w1 = w1p[q];
#pragma unroll
                for (int r = 0; r < 4; ++r) {
                    acc2[r][2*q  ] = fma2(xx0[r], w0.x, acc2[r][2*q  ]);
                    acc2[r][2*q+1] = fma2(xx0[r], w0.y, acc2[r][2*q+1]);
                    acc2[r][2*q  ] = fma2(xx1[r], w1.x, acc2[r][2*q  ]);
                    acc2[r][2*q+1] = fma2(xx1[r], w1.y, acc2[r][2*q+1]);
                }
            }
        }
        __syncthreads();
    }

#pragma unroll
    for (int r = 0; r < 4; ++r)
#pragma unroll
        for (int c = 0; c < 8; ++c) {
            float2 v = unpack2(acc2[r][c]);
            *(u64*)(Hs + (ty*4 + r)*HSTR + tx*16 + 2*c) = pack2(fast_tanh(v.x), fast_tanh(v.y));
        }
    __syncthreads();

    if (Dout == EE) {
        const int st = W2S64;
        u64 oa[4][2];
        {
            const u64* bp = (const u64*)(b2 + tx*4);
            u64 b0 = bp[0], b1v = bp[1];
#pragma unroll
            for (int r = 0; r < 4; ++r) { oa[r][0] = b0; oa[r][1] = b1v; }
        }
        for (int kk = 0; kk < 4; ++kk) {
            for (int idx = tid; idx < 64*16; idx += 128) {
                int r = idx >> 4, c4 = idx & 15;
                ((float4*)(Ws + r*st))[c4] = ((const float4*)(W2 + (size_t)(kk*64 + r)*EE))[c4];
            }
            __syncthreads();
#pragma unroll
            for (int k2 = 0; k2 < 32; ++k2) {
                u64 hh0[4], hh1[4];
#pragma unroll
                for (int r = 0; r < 4; ++r) {
                    u64 hu = *(const u64*)(Hs + (ty*4 + r)*HSTR + kk*64 + k2*2);
                    float2 hf = unpack2(hu);
                    hh0[r] = pack2(hf.x, hf.x);
                    hh1[r] = pack2(hf.y, hf.y);
                }
                const u64* w0p = (const u64*)(Ws + (k2*2    )*st + tx*4);
                const u64* w1p = (const u64*)(Ws + (k2*2 + 1)*st + tx*4);
                u64 w00 = w0p[0], w01 = w0p[1], w10 = w1p[0], w11 = w1p[1];
#pragma unroll
                for (int r = 0; r < 4; ++r) {
                    oa[r][0] = fma2(hh0[r], w00, oa[r][0]);
                    oa[r][1] = fma2(hh0[r], w01, oa[r][1]);
                    oa[r][0] = fma2(hh1[r], w10, oa[r][0]);
                    oa[r][1] = fma2(hh1[r], w11, oa[r][1]);
                }
            }
            __syncthreads();
        }
#pragma unroll
        for (int r = 0; r < 4; ++r) {
            *(u64*)(out + (size_t)(row0 + ty*4 + r)*EE + tx*4    ) = oa[r][0];
            *(u64*)(out + (size_t)(row0 + ty*4 + r)*EE + tx*4 + 2) = oa[r][1];
        }
    } else {
        const int st = W2S32;
        u64 oa[4];
        {
            u64 b0 = *(const u64*)(b2 + tx*2);
#pragma unroll
            for (int r = 0; r < 4; ++r) oa[r] = b0;
        }
        for (int kk = 0; kk < 4; ++kk) {
            for (int idx = tid; idx < 64*8; idx += 128) {
                int r = idx >> 3, c4 = idx & 7;
                ((float4*)(Ws + r*st))[c4] = ((const float4*)(W2 + (size_t)(kk*64 + r)*RR))[c4];
            }
            __syncthreads();
#pragma unroll
            for (int k2 = 0; k2 < 32; ++k2) {
                u64 hh0[4], hh1[4];
#pragma unroll
                for (int r = 0; r < 4; ++r) {
                    u64 hu = *(const u64*)(Hs + (ty*4 + r)*HSTR + kk*64 + k2*2);
                    float2 hf = unpack2(hu);
                    hh0[r] = pack2(hf.x, hf.x);
                    hh1[r] = pack2(hf.y, hf.y);
                }
                u64 w0 = *(const u64*)(Ws + (k2*2    )*st + tx*2);
                u64 w1 = *(const u64*)(Ws + (k2*2 + 1)*st + tx*2);
#pragma unroll
                for (int r = 0; r < 4; ++r) {
                    oa[r] = fma2(hh0[r], w0, oa[r]);
                    oa[r] = fma2(hh1[r], w1, oa[r]);
                }
            }
            __syncthreads();
        }
#pragma unroll
        for (int r = 0; r < 4; ++r)
            *(u64*)(out + (size_t)(row0 + ty*4 + r)*RR + tx*2) = oa[r];
    }
}

// ---------------- 3a) Gram kernel (register-tiled, f32x2) ----------------
__global__ void __launch_bounds__(128) gram_kernel() {
    __shared__ float sX[64*66];
    __shared__ float sY[64*66];
    int b = blockIdx.x, w = blockIdx.y, tid = threadIdx.x;
    size_t off64 = (size_t)b*SS*EE;
    size_t off32 = (size_t)b*SS*RR;
    const float *X, *Y;
    int D, dsh;
    if (w == 0)      { X = g_e1 + off64; Y = g_e1 + off64; D = 64; dsh = 6; }
    else if (w == 1) { X = g_e1 + off64; Y = g_e2 + off64; D = 64; dsh = 6; }
    else if (w == 2) { X = g_e2 + off64; Y = g_e2 + off64; D = 64; dsh = 6; }
    else {
        int pq = w - 3;
        const float* rb[3] = { g_r1 + off32, g_r2 + off32, g_r3 + off32 };
        const int pi[6] = {0,0,0,1,1,2};
        const int qi[6] = {0,1,2,1,2,2};
        X = rb[pi[pq]]; Y = rb[qi[pq]]; D = 32; dsh = 5;
    }
    for (int idx = tid; idx < 64*D; idx += 128) {
        int row = idx >> dsh, d = idx & (D-1);
        sX[row*66 + d] = X[idx];
        sY[row*66 + d] = Y[idx];
    }
    __syncthreads();

    int ty = tid >> 3, tx = tid & 7;
    int s0 = ty * 4, t0 = tx * 8;
    u64 acc[4][8];
#pragma unroll
    for (int i = 0; i < 4; ++i)
#pragma unroll
        for (int j = 0; j < 8; ++j) acc[i][j] = 0ull;

    int DP = D >> 1;
#pragma unroll 4
    for (int dp = 0; dp < DP; ++dp) {
        u64 x2[4], y2[8];
#pragma unroll
        for (int i = 0; i < 4; ++i) x2[i] = *(const u64*)(sX + (s0+i)*66 + 2*dp);
#pragma unroll
        for (int j = 0; j < 8; ++j) y2[j] = *(const u64*)(sY + (t0+j)*66 + 2*dp);
#pragma unroll
        for (int i = 0; i < 4; ++i)
#pragma unroll
            for (int j = 0; j < 8; ++j)
                acc[i][j] = fma2(x2[i], y2[j], acc[i][j]);
    }

    float* out = g_gram + ((size_t)(b*9 + w) << 12);
#pragma unroll
    for (int i = 0; i < 4; ++i)
#pragma unroll
        for (int j = 0; j < 8; ++j) {
            float2 p = unpack2(acc[i][j]);
            out[(s0+i)*64 + (t0+j)] = p.x + p.y;
        }
}

// ---------------- 3b) Gram-space scan: blocked forward substitution ----------------
// grid (BB, 2), block 256 (8 warps). Block size 16, 4 blocks.
// warp 0 solves diagonal block sequentially (no syncs); all warps apply rank-16
// updates to future rows in parallel. 7 block-syncs total.
#define SL_SMEM_FLOATS (9*4096 + 2*2048 + 3*2048 + 3*2048)
__global__ void __launch_bounds__(256) scanloop_kernel() {
    extern __shared__ float sm[];
    float* sCoef = sm;                  // 9 x 4096
    float* sE1h  = sm + 9*4096;         // 64 x 32
    float* sE2h  = sE1h + 2048;
    float* sA    = sE2h + 2048;         // 64 x 32
    float* sB    = sA + 2048;
    float* sC    = sB + 2048;
    float* sW    = sC + 2048;           // accumulators 64 x 32
    float* sM    = sW + 2048;
    float* sBh   = sM + 2048;

    int b = blockIdx.x, by = blockIdx.y, tid = threadIdx.x;
    int g = tid >> 5, fl = tid & 31;

    {
        const float* G = g_gram + (size_t)b*9*4096;
        for (int i = tid; i < 4096; i += 256) {
            int s = i >> 6, t = i & 63;
            int ts = (t << 6) + s;
            float ge11  = G[i];
            float ge12  = G[4096 + i];
            float ge12t = G[4096 + ts];
            float ge22  = G[2*4096 + i];
            float gr11  = G[3*4096 + i];
            float gr12  = G[4*4096 + i];
            float gr12t = G[4*4096 + ts];
            float gr13  = G[5*4096 + i];
            float gr13t = G[5*4096 + ts];
            float gr22  = G[6*4096 + i];
            float gr23  = G[7*4096 + i];
            float gr23t = G[7*4096 + ts];
            float gr33  = G[8*4096 + i];
            sCoef[          i] = ge11  * gr11;
            sCoef[  4096 +  i] = ge11  * gr12;
            sCoef[2*4096 +  i] = ge12  * gr13;
            sCoef[3*4096 +  i] = ge11  * gr12t;
            sCoef[4*4096 +  i] = ge11  * gr22;
            sCoef[5*4096 +  i] = ge12  * gr23;
            sCoef[6*4096 +  i] = ge12t * gr13t;
            sCoef[7*4096 +  i] = ge12t * gr23t;
            sCoef[8*4096 +  i] = ge22  * gr33;
        }
        for (int i = tid; i < 2048; i += 256) {
            int t = i >> 5, f2 = i & 31;
            sE1h[i] = g_e1[((size_t)(b*SS + t))*EE + (by << 5) + f2];
            sE2h[i] = g_e2[((size_t)(b*SS + t))*EE + (by << 5) + f2];
            sW[i] = 0.f; sM[i] = 0.f; sBh[i] = 0.f;
        }
    }
    __syncthreads();

    for (int j = 0; j < 4; ++j) {
        int s0 = j << 4;
        // warp 0: sequential solve of 16-step diagonal block (no block syncs)
        if (tid < 32) {
            for (int si = 0; si < 16; ++si) {
                int s = s0 + si;
                int sf = (s << 5) + fl;
                float w = sW[sf], m = sM[sf], bh = sBh[sf];
                for (int tp = 0; tp < si; ++tp) {
                    int t = s0 + tp;
                    int st = (s << 6) + t;
                    int tf = (t << 5) + fl;
                    float at = sA[tf], bt = sB[tf], ct = sC[tf];
                    w  = fmaf(sCoef[          st], at,
                          fmaf(sCoef[  4096 + st], bt,
                          fmaf(sCoef[2*4096 + st], ct, w)));
                    m  = fmaf(sCoef[3*4096 + st], at,
                          fmaf(sCoef[4*4096 + st], bt,
                          fmaf(sCoef[5*4096 + st], ct, m)));
                    bh = fmaf(sCoef[6*4096 + st], at,
                          fmaf(sCoef[7*4096 + st], bt,
                          fmaf(sCoef[8*4096 + st], ct, bh)));
                }
                float a = sE2h[sf] - w;
                float bb = w - m;
                float c = sE1h[sf] - bh;
                sA[sf] = a; sB[sf] = bb; sC[sf] = c;
            }
        }
        __syncthreads();
        // all warps: rank-16 update of future rows
        if (j < 3) {
            int base = s0 + 16;
            for (int sp = base + g; sp < 64; sp += 8) {
                float w = 0.f, m = 0.f, bh = 0.f;
#pragma unroll
                for (int tp = 0; tp < 16; ++tp) {
                    int t = s0 + tp;
                    int st = (sp << 6) + t;
                    int tf = (t << 5) + fl;
                    float at = sA[tf], bt = sB[tf], ct = sC[tf];
                    w  = fmaf(sCoef[          st], at,
                          fmaf(sCoef[  4096 + st], bt,
                          fmaf(sCoef[2*4096 + st], ct, w)));
                    m  = fmaf(sCoef[3*4096 + st], at,
                          fmaf(sCoef[4*4096 + st], bt,
                          fmaf(sCoef[5*4096 + st], ct, m)));
                    bh = fmaf(sCoef[6*4096 + st], at,
                          fmaf(sCoef[7*4096 + st], bt,
                          fmaf(sCoef[8*4096 + st], ct, bh)));
                }
                int sf = (sp << 5) + fl;
                sW[sf] += w; sM[sf] += m; sBh[sf] += bh;
            }
            __syncthreads();
        }
    }

    for (int i = tid; i < 2048; i += 256) {
        int t = i >> 5, f2 = i & 31;
        size_t base = ((size_t)(b*3)*SS + t)*EE + (by << 5) + f2;
        g_abc[base          ] = sA[i];
        g_abc[base + SS*EE  ] = sB[i];
        g_abc[base + 2*SS*EE] = sC[i];
    }
}

// ---------------- 4) inference chain ----------------
#define IF_SMEM_FLOATS (3*4096 + 2*65*64 + 6*64 + 4 + 128)
__global__ void __launch_bounds__(128) infer_kernel(
    const float* __restrict__ qe1,
    const float* __restrict__ qr1, const float* __restrict__ qr2, const float* __restrict__ qr3,
    const float* __restrict__ ln_g, const float* __restrict__ ln_b)
{
    extern __shared__ float sm[];
    float* sA   = sm;
    float* sB   = sA + 4096;
    float* sC   = sB + 4096;
    float* sE1T = sC + 4096;
    float* sE2T = sE1T + 65*64;
    float* cur  = sE2T + 65*64;
    float* d1   = cur + 64;
    float* d2   = d1 + 64;
    float* ca   = d2 + 64;
    float* cb   = ca + 64;
    float* cc   = cb + 64;
    float* lnr  = cc + 64;
    float* sPar = lnr + 4;

    int b = blockIdx.x, tid = threadIdx.x;
    int g = tid >> 6, f = tid & 63;

    {
        const float4* a4 = (const float4*)(g_abc + (size_t)(b*3)*SS*EE);
        float4* s4 = (float4*)sA;
        for (int i = tid; i < 3*1024; i += 128) s4[i] = a4[i];
        for (int i = tid; i < 4096; i += 128) {
            int tt = i >> 6, ff = i & 63;
            sE1T[ff*65 + tt] = g_e1[((size_t)(b*SS + tt))*EE + ff];
            sE2T[ff*65 + tt] = g_e2[((size_t)(b*SS + tt))*EE + ff];
        }
    }
    if (tid < 64) cur[tid] = qe1[b*EE + tid];
    __syncthreads();

    float isum = 0.f;
    for (int p = 0; p < 3; ++p) {
        const float* qrp = (p == 0 ? qr1 : (p == 1 ? qr2 : qr3)) + b*RR;
        if (tid < 64) {
            int t = tid;
            float s1 = 0.f, s2 = 0.f;
            for (int f2 = 0; f2 < 64; ++f2) {
                float cv = cur[f2];
                s1 = fmaf(cv, sE1T[f2*65 + t], s1);
                s2 = fmaf(cv, sE2T[f2*65 + t], s2);
            }
            d1[t] = s1; d2[t] = s2;
        } else {
            int t = tid - 64;
            const float* r1p = g_r1 + ((size_t)(b*SS + t))*RR;
            const float* r2p = g_r2 + ((size_t)(b*SS + t))*RR;
            const float* r3p = g_r3 + ((size_t)(b*SS + t))*RR;
            float a1 = 0.f, a2 = 0.f, a3 = 0.f;
            for (int r = 0; r < RR; ++r) {
                float q = qrp[r];
                a1 = fmaf(q, r1p[r], a1);
                a2 = fmaf(q, r2p[r], a2);
                a3 = fmaf(q, r3p[r], a3);
            }
            ca[t] = a1; cb[t] = a2; cc[t] = a3;
        }
        __syncthreads();
        if (tid < 64) {
            int t = tid;
            ca[t] *= d1[t];
            cb[t] *= d1[t];
            cc[t] *= d2[t];
        }
        __syncthreads();
        {
            float acc = 0.f;
            for (int t = g; t < 64; t += 2) {
                int tf = (t << 6) + f;
                acc = fmaf(ca[t], sA[tf], fmaf(cb[t], sB[tf], fmaf(cc[t], sC[tf], acc)));
            }
            sPar[(g << 6) + f] = acc;
        }
        __syncthreads();
        if (g == 0) {
            float raw = sPar[f] + sPar[64 + f];
            float ssum = raw;
#pragma unroll
            for (int off = 16; off > 0; off >>= 1) ssum += __shfl_xor_sync(0xffffffffu, ssum, off);
            if ((f & 31) == 0) lnr[f >> 5] = ssum;
        }
        __syncthreads();
        if (g == 0) {
            float raw = sPar[f] + sPar[64 + f];
            float mean = (lnr[0] + lnr[1]) * (1.f/64.f);
            float d = raw - mean;
            float q = d * d;
#pragma unroll
            for (int off = 16; off > 0; off >>= 1) q += __shfl_xor_sync(0xffffffffu, q, off);
            if ((f & 31) == 0) lnr[2 + (f >> 5)] = q;
        }
        __syncthreads();
        if (g == 0) {
            float raw = sPar[f] + sPar[64 + f];
            float mean = (lnr[0] + lnr[1]) * (1.f/64.f);
            float var  = (lnr[2] + lnr[3]) * (1.f/64.f);
            float val = (raw - mean) * rsqrtf(var + 1e-5f) * ln_g[p*EE + f] + ln_b[p*EE + f];
            cur[f] = val;
            isum += val;
        }
        __syncthreads();
    }
    if (g == 0) g_isum[b*EE + f] = isum;
}

// ---------------- 5) output GEMM ----------------
__global__ void __launch_bounds__(128) outgemm_kernel(const float* __restrict__ Z,
                                                      float* __restrict__ out) {
    __shared__ float sI[16][64];
    int bx = blockIdx.x, by = blockIdx.y, tid = threadIdx.x;
    for (int idx = tid; idx < 1024; idx += 128)
        sI[idx >> 6][idx & 63] = g_isum[by*1024 + idx];
    __syncthreads();

    int v = bx*128 + tid;
    float acc[16];
#pragma unroll
    for (int i = 0; i < 16; ++i) acc[i] = 0.f;
#pragma unroll 4
    for (int e = 0; e < 64; ++e) {
        float z = __ldg(Z + (size_t)e*VV + v);
#pragma unroll
        for (int i = 0; i < 16; ++i)
            acc[i] = fmaf(sI[i][e], z, acc[i]);
    }
#pragma unroll
    for (int i = 0; i < 16; ++i)
        out[(size_t)(by*16 + i)*VV + v] = acc[i];
}

// ---------------- launch ----------------
extern "C" void kernel_launch(void* const* d_in, const int* in_sizes, int n_in,
                              void* d_out, int out_size) {
    const int*   story = (const int*)d_in[0];
    const int*   query = (const int*)d_in[1];
    const float* WE    = (const float*)d_in[2];
    const float* PE    = (const float*)d_in[3];
    const float* ue_W1 = (const float*)d_in[4];
    const float* ue_b1 = (const float*)d_in[5];
    const float* ue_W2 = (const float*)d_in[6];
    const float* ue_b2 = (const float*)d_in[7];
    const float* ur_W1 = (const float*)d_in[8];
    const float* ur_b1 = (const float*)d_in[9];
    const float* ur_W2 = (const float*)d_in[10];
    const float* ur_b2 = (const float*)d_in[11];
    const float* ie_W1 = (const float*)d_in[12];
    const float* ie_b1 = (const float*)d_in[13];
    const float* ie_W2 = (const float*)d_in[14];
    const float* ie_b2 = (const float*)d_in[15];
    const float* ir_W1 = (const float*)d_in[16];
    const float* ir_b1 = (const float*)d_in[17];
    const float* ir_W2 = (const float*)d_in[18];
    const float* ir_b2 = (const float*)d_in[19];
    const float* ln_g  = (const float*)d_in[20];
    const float* ln_b  = (const float*)d_in[21];
    const float* Z     = (const float*)d_in[22];
    float* out = (float*)d_out;

    const int MLP_SMEM = MLP_SMEM_FLOATS * (int)sizeof(float);
    const int SL_SMEM  = SL_SMEM_FLOATS * (int)sizeof(float);   // 212,992 B
    const int IF_SMEM  = IF_SMEM_FLOATS * (int)sizeof(float);
    cudaFuncSetAttribute(mlp5_kernel, cudaFuncAttributeMaxDynamicSharedMemorySize, MLP_SMEM);
    cudaFuncSetAttribute(scanloop_kernel, cudaFuncAttributeMaxDynamicSharedMemorySize, SL_SMEM);
    cudaFuncSetAttribute(infer_kernel, cudaFuncAttributeMaxDynamicSharedMemorySize, IF_SMEM);

    float *d_sent, *d_qsum, *d_e1, *d_e2, *d_r1, *d_r2, *d_r3;
    float *d_qe1, *d_qe2, *d_qr1, *d_qr2, *d_qr3;
    cudaGetSymbolAddress((void**)&d_sent, g_sent);
    cudaGetSymbolAddress((void**)&d_qsum, g_qsum);
    cudaGetSymbolAddress((void**)&d_e1, g_e1);
    cudaGetSymbolAddress((void**)&d_e2, g_e2);
    cudaGetSymbolAddress((void**)&d_r1, g_r1);
    cudaGetSymbolAddress((void**)&d_r2, g_r2);
    cudaGetSymbolAddress((void**)&d_r3, g_r3);
    cudaGetSymbolAddress((void**)&d_qe1, g_qe1);
    cudaGetSymbolAddress((void**)&d_qe2, g_qe2);
    cudaGetSymbolAddress((void**)&d_qr1, g_qr1);
    cudaGetSymbolAddress((void**)&d_qr2, g_qr2);
    cudaGetSymbolAddress((void**)&d_qr3, g_qr3);

    embed_kernel<<<BB*SS + BB, SYM>>>(story, query, WE, PE);

    mlp5_kernel<<<dim3(BB*SS/32 + 2, 5), 128, MLP_SMEM>>>(
        d_sent, d_qsum,
        ue_W1, ue_b1, ue_W2, ue_b2, ur_W1, ur_b1, ur_W2, ur_b2,
        ie_W1, ie_b1, ie_W2, ie_b2, ir_W1, ir_b1, ir_W2, ir_b2,
        d_e1, d_e2, d_r1, d_r2, d_r3,
        d_qe1, d_qe2, d_qr1, d_qr2, d_qr3);

    gram_kernel<<<dim3(BB, 9), 128>>>();
    scanloop_kernel<<<dim3(BB, 2), 256, SL_SMEM>>>();
    infer_kernel<<<BB, 128, IF_SMEM>>>(d_qe1, d_qr1, d_qr2, d_qr3, ln_g, ln_b);
    outgemm_kernel<<<dim3(VV/128, BB/16), 128>>>(Z, out);
}

// round 15
// speedup vs baseline: 1.0745x; 1.0302x over previous
#include <cuda_runtime.h>
#include <cuda_bf16.h>
#include <math.h>

#define BB 64
#define SS 64
#define WW 12
#define SYM 128
#define HID 256
#define EE 64
#define RR 32
#define VV 32000

typedef unsigned long long u64;

__device__ __align__(16) float g_sent[BB*SS*SYM];
__device__ __align__(16) float g_qsum[BB*SYM];
__device__ __align__(16) float g_e1[BB*SS*EE];
__device__ __align__(16) float g_e2[BB*SS*EE];
__device__ __align__(16) float g_r1[BB*SS*RR];
__device__ __align__(16) float g_r2[BB*SS*RR];
__device__ __align__(16) float g_r3[BB*SS*RR];
__device__ __align__(16) float g_qe1[BB*EE];
__device__ __align__(16) float g_qe2[BB*EE];
__device__ __align__(16) float g_qr1[BB*RR];
__device__ __align__(16) float g_qr2[BB*RR];
__device__ __align__(16) float g_qr3[BB*RR];
__device__ __align__(16) float g_gram[(size_t)BB*9*SS*SS];   // raw grams
__device__ __align__(16) float g_coef[(size_t)BB*9*SS*SS];   // precomputed coefficient planes
__device__ __align__(16) float g_abc[(size_t)BB*3*SS*EE];
__device__ __align__(16) float g_isum[BB*EE];

__device__ __forceinline__ u64 fma2(u64 a, u64 b, u64 c) {
    u64 d;
    asm("fma.rn.f32x2 %0, %1, %2, %3;" : "=l"(d) : "l"(a), "l"(b), "l"(c));
    return d;
}
__device__ __forceinline__ float2 unpack2(u64 a) {
    float2 r;
    asm("mov.b64 {%0,%1}, %2;" : "=f"(r.x), "=f"(r.y) : "l"(a));
    return r;
}
__device__ __forceinline__ u64 pack2(float x, float y) {
    u64 r;
    asm("mov.b64 %0, {%1,%2};" : "=l"(r) : "f"(x), "f"(y));
    return r;
}
__device__ __forceinline__ float fast_tanh(float x) {
    float e = __expf(2.f * x);
    return 1.f - __fdividef(2.f, e + 1.f);
}

// ---------------- 1) embedding ----------------
__global__ void embed_kernel(const int* __restrict__ story, const int* __restrict__ query,
                             const float* __restrict__ WE, const float* __restrict__ PE) {
    int r = blockIdx.x;
    int e = threadIdx.x;
    const int* idx;
    float* dst;
    if (r < BB*SS) { idx = story + r*WW; dst = g_sent + r*SYM; }
    else           { int rb = r - BB*SS; idx = query + rb*WW; dst = g_qsum + rb*SYM; }
    float acc = 0.f;
#pragma unroll
    for (int w = 0; w < WW; ++w) {
        int t = __ldg(idx + w);
        acc = fmaf(WE[(size_t)t*SYM + e], PE[w*SYM + e], acc);
    }
    dst[e] = acc;
}

// ---------------- 2) fused 5-head MLP (R11 structure, fast_tanh) ----------------
#define XSTR 132
#define W1S 260
#define W2S64 68
#define W2S32 36
#define HSTR 260
#define WREG 4352
#define MLP_SMEM_FLOATS (32*XSTR + WREG + 32*HSTR)
__global__ void __launch_bounds__(128) mlp5_kernel(
    const float* __restrict__ Xs_story, const float* __restrict__ Xs_query,
    const float* __restrict__ ueW1, const float* __restrict__ ueb1,
    const float* __restrict__ ueW2, const float* __restrict__ ueb2,
    const float* __restrict__ urW1, const float* __restrict__ urb1,
    const float* __restrict__ urW2, const float* __restrict__ urb2,
    const float* __restrict__ ieW1, const float* __restrict__ ieb1,
    const float* __restrict__ ieW2, const float* __restrict__ ieb2,
    const float* __restrict__ irW1, const float* __restrict__ irb1,
    const float* __restrict__ irW2, const float* __restrict__ irb2,
    float* __restrict__ so0, float* __restrict__ so1,
    float* __restrict__ so2, float* __restrict__ so3, float* __restrict__ so4,
    float* __restrict__ qo0, float* __restrict__ qo1,
    float* __restrict__ qo2, float* __restrict__ qo3, float* __restrict__ qo4)
{
    extern __shared__ float smm[];
    float* Xs = smm;
    float* Ws = Xs + 32*XSTR;
    float* Hs = Ws + WREG;

    int h = blockIdx.y;
    bool is_q = (blockIdx.x >= BB*SS/32);
    const float* X = is_q ? Xs_query : Xs_story;
    int row0 = (is_q ? (blockIdx.x - BB*SS/32) : blockIdx.x) * 32;

    const float *eW1 = is_q ? ieW1 : ueW1, *eb1 = is_q ? ieb1 : ueb1;
    const float *eW2 = is_q ? ieW2 : ueW2, *eb2 = is_q ? ieb2 : ueb2;
    const float *rW1 = is_q ? irW1 : urW1, *rb1 = is_q ? irb1 : urb1;
    const float *rW2 = is_q ? irW2 : urW2, *rb2 = is_q ? irb2 : urb2;

    const float *W1, *b1, *W2, *b2;
    float* out;
    int Dout;
    if (h < 2) {
        W1 = eW1 + (size_t)h*SYM*HID; b1 = eb1 + h*HID;
        W2 = eW2 + (size_t)h*HID*EE;  b2 = eb2 + h*EE;
        out = h ? (is_q ? qo1 : so1) : (is_q ? qo0 : so0); Dout = EE;
    } else {
        int g = h - 2;
        W1 = rW1 + (size_t)g*SYM*HID; b1 = rb1 + g*HID;
        W2 = rW2 + (size_t)g*HID*RR;  b2 = rb2 + g*RR;
        out = (g == 0) ? (is_q ? qo2 : so2)
            : ((g == 1) ? (is_q ? qo3 : so3) : (is_q ? qo4 : so4));
        Dout = RR;
    }

    int tid = threadIdx.x;
    int ty = tid >> 4, tx = tid & 15;

    for (int idx = tid; idx < 32*32; idx += 128) {
        int r = idx >> 5, c4 = idx & 31;
        ((float4*)(Xs + r*XSTR))[c4] = ((const float4*)(X + (size_t)(row0 + r)*SYM))[c4];
    }

    u64 acc2[4][8];
    {
        const u64* bp = (const u64*)(b1 + tx*16);
#pragma unroll
        for (int c = 0; c < 8; ++c) {
            u64 bv = bp[c];
#pragma unroll
            for (int r = 0; r < 4; ++r) acc2[r][c] = bv;
        }
    }
    __syncthreads();

    for (int kk = 0; kk < 8; ++kk) {
        for (int idx = tid; idx < 16*64; idx += 128) {
            int r = idx >> 6, c4 = idx & 63;
            ((float4*)(Ws + r*W1S))[c4] = ((const float4*)(W1 + (size_t)(kk*16 + r)*HID))[c4];
        }
        __syncthreads();
#pragma unroll
        for (int k2 = 0; k2 < 8; ++k2) {
            u64 xx0[4], xx1[4];
#pragma unroll
            for (int r = 0; r < 4; ++r) {
                u64 xu = *(const u64*)(Xs + (ty*4 + r)*XSTR + kk*16 + k2*2);
                float2 xf = unpack2(xu);
                xx0[r] = pack2(xf.x, xf.x);
                xx1[r] = pack2(xf.y, xf.y);
            }
            const ulonglong2* w0p = (const ulonglong2*)(Ws + (k2*2    )*W1S + tx*16);
            const ulonglong2* w1p = (const ulonglong2*)(Ws + (k2*2 + 1)*W1S + tx*16);
#pragma unroll
            for (int q = 0; q < 4; ++q) {
                ulonglong2 w0 = w0p[q];
                ulonglong2 w1 = w1p[q];
#pragma unroll
                for (int r = 0; r < 4; ++r) {
                    acc2[r][2*q  ] = fma2(xx0[r], w0.x, acc2[r][2*q  ]);
                    acc2[r][2*q+1] = fma2(xx0[r], w0.y, acc2[r][2*q+1]);
                    acc2[r][2*q  ] = fma2(xx1[r], w1.x, acc2[r][2*q  ]);
                    acc2[r][2*q+1] = fma2(xx1[r], w1.y, acc2[r][2*q+1]);
                }
            }
        }
        __syncthreads();
    }

#pragma unroll
    for (int r = 0; r < 4; ++r)
#pragma unroll
        for (int c = 0; c < 8; ++c) {
            float2 v = unpack2(acc2[r][c]);
            *(u64*)(Hs + (ty*4 + r)*HSTR + tx*16 + 2*c) = pack2(fast_tanh(v.x), fast_tanh(v.y));
        }
    __syncthreads();

    if (Dout == EE) {
        const int st = W2S64;
        u64 oa[4][2];
        {
            const u64* bp = (const u64*)(b2 + tx*4);
            u64 b0 = bp[0], b1v = bp[1];
#pragma unroll
            for (int r = 0; r < 4; ++r) { oa[r][0] = b0; oa[r][1] = b1v; }
        }
        for (int kk = 0; kk < 4; ++kk) {
            for (int idx = tid; idx < 64*16; idx += 128) {
                int r = idx >> 4, c4 = idx & 15;
                ((float4*)(Ws + r*st))[c4] = ((const float4*)(W2 + (size_t)(kk*64 + r)*EE))[c4];
            }
            __syncthreads();
#pragma unroll
            for (int k2 = 0; k2 < 32; ++k2) {
                u64 hh0[4], hh1[4];
#pragma unroll
                for (int r = 0; r < 4; ++r) {
                    u64 hu = *(const u64*)(Hs + (ty*4 + r)*HSTR + kk*64 + k2*2);
                    float2 hf = unpack2(hu);
                    hh0[r] = pack2(hf.x, hf.x);
                    hh1[r] = pack2(hf.y, hf.y);
                }
                const u64* w0p = (const u64*)(Ws + (k2*2    )*st + tx*4);
                const u64* w1p = (const u64*)(Ws + (k2*2 + 1)*st + tx*4);
                u64 w00 = w0p[0], w01 = w0p[1], w10 = w1p[0], w11 = w1p[1];
#pragma unroll
                for (int r = 0; r < 4; ++r) {
                    oa[r][0] = fma2(hh0[r], w00, oa[r][0]);
                    oa[r][1] = fma2(hh0[r], w01, oa[r][1]);
                    oa[r][0] = fma2(hh1[r], w10, oa[r][0]);
                    oa[r][1] = fma2(hh1[r], w11, oa[r][1]);
                }
            }
            __syncthreads();
        }
#pragma unroll
        for (int r = 0; r < 4; ++r) {
            *(u64*)(out + (size_t)(row0 + ty*4 + r)*EE + tx*4    ) = oa[r][0];
            *(u64*)(out + (size_t)(row0 + ty*4 + r)*EE + tx*4 + 2) = oa[r][1];
        }
    } else {
        const int st = W2S32;
        u64 oa[4];
        {
            u64 b0 = *(const u64*)(b2 + tx*2);
#pragma unroll
            for (int r = 0; r < 4; ++r) oa[r] = b0;
        }
        for (int kk = 0; kk < 4; ++kk) {
            for (int idx = tid; idx < 64*8; idx += 128) {
                int r = idx >> 3, c4 = idx & 7;
                ((float4*)(Ws + r*st))[c4] = ((const float4*)(W2 + (size_t)(kk*64 + r)*RR))[c4];
            }
            __syncthreads();
#pragma unroll
            for (int k2 = 0; k2 < 32; ++k2) {
                u64 hh0[4], hh1[4];
#pragma unroll
                for (int r = 0; r < 4; ++r) {
                    u64 hu = *(const u64*)(Hs + (ty*4 + r)*HSTR + kk*64 + k2*2);
                    float2 hf = unpack2(hu);
                    hh0[r] = pack2(hf.x, hf.x);
                    hh1[r] = pack2(hf.y, hf.y);
                }
                u64 w0 = *(const u64*)(Ws + (k2*2    )*st + tx*2);
                u64 w1 = *(const u64*)(Ws + (k2*2 + 1)*st + tx*2);
#pragma unroll
                for (int r = 0; r < 4; ++r) {
                    oa[r] = fma2(hh0[r], w0, oa[r]);
                    oa[r] = fma2(hh1[r], w1, oa[r]);
                }
            }
            __syncthreads();
        }
#pragma unroll
        for (int r = 0; r < 4; ++r)
            *(u64*)(out + (size_t)(row0 + ty*4 + r)*RR + tx*2) = oa[r];
    }
}

// ---------------- 3a) Gram kernel (register-tiled, f32x2) ----------------
__global__ void __launch_bounds__(128) gram_kernel() {
    __shared__ float sX[64*66];
    __shared__ float sY[64*66];
    int b = blockIdx.x, w = blockIdx.y, tid = threadIdx.x;
    size_t off64 = (size_t)b*SS*EE;
    size_t off32 = (size_t)b*SS*RR;
    const float *X, *Y;
    int D, dsh;
    if (w == 0)      { X = g_e1 + off64; Y = g_e1 + off64; D = 64; dsh = 6; }
    else if (w == 1) { X = g_e1 + off64; Y = g_e2 + off64; D = 64; dsh = 6; }
    else if (w == 2) { X = g_e2 + off64; Y = g_e2 + off64; D = 64; dsh = 6; }
    else {
        int pq = w - 3;
        const float* rb[3] = { g_r1 + off32, g_r2 + off32, g_r3 + off32 };
        const int pi[6] = {0,0,0,1,1,2};
        const int qi[6] = {0,1,2,1,2,2};
        X = rb[pi[pq]]; Y = rb[qi[pq]]; D = 32; dsh = 5;
    }
    for (int idx = tid; idx < 64*D; idx += 128) {
        int row = idx >> dsh, d = idx & (D-1);
        sX[row*66 + d] = X[idx];
        sY[row*66 + d] = Y[idx];
    }
    __syncthreads();

    int ty = tid >> 3, tx = tid & 7;
    int s0 = ty * 4, t0 = tx * 8;
    u64 acc[4][8];
#pragma unroll
    for (int i = 0; i < 4; ++i)
#pragma unroll
        for (int j = 0; j < 8; ++j) acc[i][j] = 0ull;

    int DP = D >> 1;
#pragma unroll 4
    for (int dp = 0; dp < DP; ++dp) {
        u64 x2[4], y2[8];
#pragma unroll
        for (int i = 0; i < 4; ++i) x2[i] = *(const u64*)(sX + (s0+i)*66 + 2*dp);
#pragma unroll
        for (int j = 0; j < 8; ++j) y2[j] = *(const u64*)(sY + (t0+j)*66 + 2*dp);
#pragma unroll
        for (int i = 0; i < 4; ++i)
#pragma unroll
            for (int j = 0; j < 8; ++j)
                acc[i][j] = fma2(x2[i], y2[j], acc[i][j]);
    }

    float* out = g_gram + ((size_t)(b*9 + w) << 12);
#pragma unroll
    for (int i = 0; i < 4; ++i)
#pragma unroll
        for (int j = 0; j < 8; ++j) {
            float2 p = unpack2(acc[i][j]);
            out[(s0+i)*64 + (t0+j)] = p.x + p.y;
        }
}

// ---------------- 3b) coefficient kernel: fully parallel gram-product ----------------
// coef plane w at (s,t): E[eP](s,t or t,s) * R[rP](s,t or t,s)
// w: 0 ge11*gr11 | 1 ge11*gr12 | 2 ge12*gr13 | 3 ge11*gr12^T | 4 ge11*gr22
//    5 ge12*gr23 | 6 ge12^T*gr13^T | 7 ge12^T*gr23^T | 8 ge22*gr33
__global__ void __launch_bounds__(256) coef_kernel() {
    const int eP[9] = {0,0,1,0,0,1,1,1,2};
    const int eT[9] = {0,0,0,0,0,0,1,1,0};
    const int rP[9] = {3,4,5,4,6,7,5,7,8};
    const int rT[9] = {0,0,0,1,0,0,1,1,0};
    int b = blockIdx.x, w = blockIdx.y, tid = threadIdx.x;
    const float* G = g_gram + (size_t)b*9*4096;
    const float* Ge = G + eP[w]*4096;
    const float* Gr = G + rP[w]*4096;
    float* out = g_coef + ((size_t)(b*9 + w) << 12);
    bool et = eT[w], rt = rT[w];
    for (int i = tid; i < 4096; i += 256) {
        int s = i >> 6, t = i & 63;
        int ts = (t << 6) + s;
        float ev = Ge[et ? ts : i];
        float rv = Gr[rt ? ts : i];
        out[i] = ev * rv;
    }
}

// ---------------- 3c) Gram-space scan, paired steps (R11-proven): grid (BB,2), block 256 ----
#define SL_SMEM_FLOATS (9*4096 + 5*2048 + 1536)
__global__ void __launch_bounds__(256) scanloop_kernel() {
    extern __shared__ float sm[];
    float* sCoef = sm;
    float* sAh   = sm + 9*4096;
    float* sBh   = sAh + 2048;
    float* sCh   = sBh + 2048;
    float* sE1h  = sCh + 2048;
    float* sE2h  = sE1h + 2048;
    float* sP    = sE2h + 2048;   // 6 x 256

    int b = blockIdx.x, by = blockIdx.y, tid = threadIdx.x;
    int g = tid >> 5, fl = tid & 31;

    {
        // bulk copy precomputed coefficients (float4)
        const float4* c4 = (const float4*)(g_coef + (size_t)b*9*4096);
        float4* s4 = (float4*)sCoef;
        for (int i = tid; i < 9216; i += 256) s4[i] = c4[i];
        for (int i = tid; i < 2048; i += 256) {
            int t = i >> 5, f2 = i & 31;
            sE1h[i] = g_e1[((size_t)(b*SS + t))*EE + (by << 5) + f2];
            sE2h[i] = g_e2[((size_t)(b*SS + t))*EE + (by << 5) + f2];
        }
    }
    __syncthreads();

    for (int s = 0; s < SS; s += 2) {
        int row0 = s << 6, row1 = (s + 1) << 6;
        float wa0=0.f, wb0=0.f, wc0=0.f, ma0=0.f, mb0=0.f, mc0=0.f, ba0=0.f, bb0=0.f, bc0=0.f;
        float wa1=0.f, wb1=0.f, wc1=0.f, ma1=0.f, mb1=0.f, mc1=0.f, ba1=0.f, bb1=0.f, bc1=0.f;
        for (int t = g; t < s; t += 8) {
            int tf = (t << 5) + fl;
            float at = sAh[tf], bt = sBh[tf], ct = sCh[tf];
            int s0t = row0 + t, s1t = row1 + t;
            wa0 = fmaf(sCoef[          s0t], at, wa0);
            wb0 = fmaf(sCoef[  4096 + s0t], bt, wb0);
            wc0 = fmaf(sCoef[2*4096 + s0t], ct, wc0);
            ma0 = fmaf(sCoef[3*4096 + s0t], at, ma0);
            mb0 = fmaf(sCoef[4*4096 + s0t], bt, mb0);
            mc0 = fmaf(sCoef[5*4096 + s0t], ct, mc0);
            ba0 = fmaf(sCoef[6*4096 + s0t], at, ba0);
            bb0 = fmaf(sCoef[7*4096 + s0t], bt, bb0);
            bc0 = fmaf(sCoef[8*4096 + s0t], ct, bc0);
            wa1 = fmaf(sCoef[          s1t], at, wa1);
            wb1 = fmaf(sCoef[  4096 + s1t], bt, wb1);
            wc1 = fmaf(sCoef[2*4096 + s1t], ct, wc1);
            ma1 = fmaf(sCoef[3*4096 + s1t], at, ma1);
            mb1 = fmaf(sCoef[4*4096 + s1t], bt, mb1);
            mc1 = fmaf(sCoef[5*4096 + s1t], ct, mc1);
            ba1 = fmaf(sCoef[6*4096 + s1t], at, ba1);
            bb1 = fmaf(sCoef[7*4096 + s1t], bt, bb1);
            bc1 = fmaf(sCoef[8*4096 + s1t], ct, bc1);
        }
        int pi = (g << 5) + fl;
        sP[         pi] = (wa0 + wb0) + wc0;
        sP[  256 +  pi] = (ma0 + mb0) + mc0;
        sP[2*256 +  pi] = (ba0 + bb0) + bc0;
        sP[3*256 +  pi] = (wa1 + wb1) + wc1;
        sP[4*256 +  pi] = (ma1 + mb1) + mc1;
        sP[5*256 +  pi] = (ba1 + bb1) + bc1;
        __syncthreads();
        if (tid < 32) {
            float w0 = 0.f, m0 = 0.f, bh0 = 0.f, w1 = 0.f, m1 = 0.f, bh1 = 0.f;
#pragma unroll
            for (int q = 0; q < 8; ++q) {
                int qi = (q << 5) + tid;
                w0  += sP[         qi];
                m0  += sP[  256 +  qi];
                bh0 += sP[2*256 +  qi];
                w1  += sP[3*256 +  qi];
                m1  += sP[4*256 +  qi];
                bh1 += sP[5*256 +  qi];
            }
            int rw0 = (s << 5) + tid;
            int rw1 = rw0 + 32;
            float a0 = sE2h[rw0] - w0;
            float b0 = w0 - m0;
            float c0 = sE1h[rw0] - bh0;
            sAh[rw0] = a0; sBh[rw0] = b0; sCh[rw0] = c0;
            int st = row1 + s;
            w1  += sCoef[          st]*a0 + sCoef[  4096 + st]*b0 + sCoef[2*4096 + st]*c0;
            m1  += sCoef[3*4096 + st]*a0 + sCoef[4*4096 + st]*b0 + sCoef[5*4096 + st]*c0;
            bh1 += sCoef[6*4096 + st]*a0 + sCoef[7*4096 + st]*b0 + sCoef[8*4096 + st]*c0;
            sAh[rw1] = sE2h[rw1] - w1;
            sBh[rw1] = w1 - m1;
            sCh[rw1] = sE1h[rw1] - bh1;
        }
        __syncthreads();
    }

    for (int i = tid; i < 2048; i += 256) {
        int t = i >> 5, f2 = i & 31;
        size_t base = ((size_t)(b*3)*SS + t)*EE + (by << 5) + f2;
        g_abc[base          ] = sAh[i];
        g_abc[base + SS*EE  ] = sBh[i];
        g_abc[base + 2*SS*EE] = sCh[i];
    }
}

// ---------------- 4) inference chain ----------------
#define IF_SMEM_FLOATS (3*4096 + 2*65*64 + 6*64 + 4 + 128)
__global__ void __launch_bounds__(128) infer_kernel(
    const float* __restrict__ qe1,
    const float* __restrict__ qr1, const float* __restrict__ qr2, const float* __restrict__ qr3,
    const float* __restrict__ ln_g, const float* __restrict__ ln_b)
{
    extern __shared__ float sm[];
    float* sA   = sm;
    float* sB   = sA + 4096;
    float* sC   = sB + 4096;
    float* sE1T = sC + 4096;
    float* sE2T = sE1T + 65*64;
    float* cur  = sE2T + 65*64;
    float* d1   = cur + 64;
    float* d2   = d1 + 64;
    float* ca   = d2 + 64;
    float* cb   = ca + 64;
    float* cc   = cb + 64;
    float* lnr  = cc + 64;
    float* sPar = lnr + 4;

    int b = blockIdx.x, tid = threadIdx.x;
    int g = tid >> 6, f = tid & 63;

    {
        const float4* a4 = (const float4*)(g_abc + (size_t)(b*3)*SS*EE);
        float4* s4 = (float4*)sA;
        for (int i = tid; i < 3*1024; i += 128) s4[i] = a4[i];
        for (int i = tid; i < 4096; i += 128) {
            int tt = i >> 6, ff = i & 63;
            sE1T[ff*65 + tt] = g_e1[((size_t)(b*SS + tt))*EE + ff];
            sE2T[ff*65 + tt] = g_e2[((size_t)(b*SS + tt))*EE + ff];
        }
    }
    if (tid < 64) cur[tid] = qe1[b*EE + tid];
    __syncthreads();

    float isum = 0.f;
    for (int p = 0; p < 3; ++p) {
        const float* qrp = (p == 0 ? qr1 : (p == 1 ? qr2 : qr3)) + b*RR;
        if (tid < 64) {
            int t = tid;
            float s1 = 0.f, s2 = 0.f;
            for (int f2 = 0; f2 < 64; ++f2) {
                float cv = cur[f2];
                s1 = fmaf(cv, sE1T[f2*65 + t], s1);
                s2 = fmaf(cv, sE2T[f2*65 + t], s2);
            }
            d1[t] = s1; d2[t] = s2;
        } else {
            int t = tid - 64;
            const float* r1p = g_r1 + ((size_t)(b*SS + t))*RR;
            const float* r2p = g_r2 + ((size_t)(b*SS + t))*RR;
            const float* r3p = g_r3 + ((size_t)(b*SS + t))*RR;
            float a1 = 0.f, a2 = 0.f, a3 = 0.f;
            for (int r = 0; r < RR; ++r) {
                float q = qrp[r];
                a1 = fmaf(q, r1p[r], a1);
                a2 = fmaf(q, r2p[r], a2);
                a3 = fmaf(q, r3p[r], a3);
            }
            ca[t] = a1; cb[t] = a2; cc[t] = a3;
        }
        __syncthreads();
        if (tid < 64) {
            int t = tid;
            ca[t] *= d1[t];
            cb[t] *= d1[t];
            cc[t] *= d2[t];
        }
        __syncthreads();
        {
            float acc = 0.f;
            for (int t = g; t < 64; t += 2) {
                int tf = (t << 6) + f;
                acc = fmaf(ca[t], sA[tf], fmaf(cb[t], sB[tf], fmaf(cc[t], sC[tf], acc)));
            }
            sPar[(g << 6) + f] = acc;
        }
        __syncthreads();
        if (g == 0) {
            float raw = sPar[f] + sPar[64 + f];
            float ssum = raw;
#pragma unroll
            for (int off = 16; off > 0; off >>= 1) ssum += __shfl_xor_sync(0xffffffffu, ssum, off);
            if ((f & 31) == 0) lnr[f >> 5] = ssum;
        }
        __syncthreads();
        if (g == 0) {
            float raw = sPar[f] + sPar[64 + f];
            float mean = (lnr[0] + lnr[1]) * (1.f/64.f);
            float d = raw - mean;
            float q = d * d;
#pragma unroll
            for (int off = 16; off > 0; off >>= 1) q += __shfl_xor_sync(0xffffffffu, q, off);
            if ((f & 31) == 0) lnr[2 + (f >> 5)] = q;
        }
        __syncthreads();
        if (g == 0) {
            float raw = sPar[f] + sPar[64 + f];
            float mean = (lnr[0] + lnr[1]) * (1.f/64.f);
            float var  = (lnr[2] + lnr[3]) * (1.f/64.f);
            float val = (raw - mean) * rsqrtf(var + 1e-5f) * ln_g[p*EE + f] + ln_b[p*EE + f];
            cur[f] = val;
            isum += val;
        }
        __syncthreads();
    }
    if (g == 0) g_isum[b*EE + f] = isum;
}

// ---------------- 5) output GEMM ----------------
__global__ void __launch_bounds__(128) outgemm_kernel(const float* __restrict__ Z,
                                                      float* __restrict__ out) {
    __shared__ float sI[16][64];
    int bx = blockIdx.x, by = blockIdx.y, tid = threadIdx.x;
    for (int idx = tid; idx < 1024; idx += 128)
        sI[idx >> 6][idx & 63] = g_isum[by*1024 + idx];
    __syncthreads();

    int v = bx*128 + tid;
    float acc[16];
#pragma unroll
    for (int i = 0; i < 16; ++i) acc[i] = 0.f;
#pragma unroll 4
    for (int e = 0; e < 64; ++e) {
        float z = __ldg(Z + (size_t)e*VV + v);
#pragma unroll
        for (int i = 0; i < 16; ++i)
            acc[i] = fmaf(sI[i][e], z, acc[i]);
    }
#pragma unroll
    for (int i = 0; i < 16; ++i)
        out[(size_t)(by*16 + i)*VV + v] = acc[i];
}

// ---------------- launch ----------------
extern "C" void kernel_launch(void* const* d_in, const int* in_sizes, int n_in,
                              void* d_out, int out_size) {
    const int*   story = (const int*)d_in[0];
    const int*   query = (const int*)d_in[1];
    const float* WE    = (const float*)d_in[2];
    const float* PE    = (const float*)d_in[3];
    const float* ue_W1 = (const float*)d_in[4];
    const float* ue_b1 = (const float*)d_in[5];
    const float* ue_W2 = (const float*)d_in[6];
    const float* ue_b2 = (const float*)d_in[7];
    const float* ur_W1 = (const float*)d_in[8];
    const float* ur_b1 = (const float*)d_in[9];
    const float* ur_W2 = (const float*)d_in[10];
    const float* ur_b2 = (const float*)d_in[11];
    const float* ie_W1 = (const float*)d_in[12];
    const float* ie_b1 = (const float*)d_in[13];
    const float* ie_W2 = (const float*)d_in[14];
    const float* ie_b2 = (const float*)d_in[15];
    const float* ir_W1 = (const float*)d_in[16];
    const float* ir_b1 = (const float*)d_in[17];
    const float* ir_W2 = (const float*)d_in[18];
    const float* ir_b2 = (const float*)d_in[19];
    const float* ln_g  = (const float*)d_in[20];
    const float* ln_b  = (const float*)d_in[21];
    const float* Z     = (const float*)d_in[22];
    float* out = (float*)d_out;

    const int MLP_SMEM = MLP_SMEM_FLOATS * (int)sizeof(float);
    const int SL_SMEM  = SL_SMEM_FLOATS * (int)sizeof(float);   // 194,560 B
    const int IF_SMEM  = IF_SMEM_FLOATS * (int)sizeof(float);
    cudaFuncSetAttribute(mlp5_kernel, cudaFuncAttributeMaxDynamicSharedMemorySize, MLP_SMEM);
    cudaFuncSetAttribute(scanloop_kernel, cudaFuncAttributeMaxDynamicSharedMemorySize, SL_SMEM);
    cudaFuncSetAttribute(infer_kernel, cudaFuncAttributeMaxDynamicSharedMemorySize, IF_SMEM);

    float *d_sent, *d_qsum, *d_e1, *d_e2, *d_r1, *d_r2, *d_r3;
    float *d_qe1, *d_qe2, *d_qr1, *d_qr2, *d_qr3;
    cudaGetSymbolAddress((void**)&d_sent, g_sent);
    cudaGetSymbolAddress((void**)&d_qsum, g_qsum);
    cudaGetSymbolAddress((void**)&d_e1, g_e1);
    cudaGetSymbolAddress((void**)&d_e2, g_e2);
    cudaGetSymbolAddress((void**)&d_r1, g_r1);
    cudaGetSymbolAddress((void**)&d_r2, g_r2);
    cudaGetSymbolAddress((void**)&d_r3, g_r3);
    cudaGetSymbolAddress((void**)&d_qe1, g_qe1);
    cudaGetSymbolAddress((void**)&d_qe2, g_qe2);
    cudaGetSymbolAddress((void**)&d_qr1, g_qr1);
    cudaGetSymbolAddress((void**)&d_qr2, g_qr2);
    cudaGetSymbolAddress((void**)&d_qr3, g_qr3);

    embed_kernel<<<BB*SS + BB, SYM>>>(story, query, WE, PE);

    mlp5_kernel<<<dim3(BB*SS/32 + 2, 5), 128, MLP_SMEM>>>(
        d_sent, d_qsum,
        ue_W1, ue_b1, ue_W2, ue_b2, ur_W1, ur_b1, ur_W2, ur_b2,
        ie_W1, ie_b1, ie_W2, ie_b2, ir_W1, ir_b1, ir_W2, ir_b2,
        d_e1, d_e2, d_r1, d_r2, d_r3,
        d_qe1, d_qe2, d_qr1, d_qr2, d_qr3);

    gram_kernel<<<dim3(BB, 9), 128>>>();
    coef_kernel<<<dim3(BB, 9), 256>>>();
    scanloop_kernel<<<dim3(BB, 2), 256, SL_SMEM>>>();
    infer_kernel<<<BB, 128, IF_SMEM>>>(d_qe1, d_qr1, d_qr2, d_qr3, ln_g, ln_b);
    outgemm_kernel<<<dim3(VV/128, BB/16), 128>>>(Z, out);
}

// round 16
// speedup vs baseline: 1.0829x; 1.0078x over previous
#include <cuda_runtime.h>
#include <cuda_bf16.h>
#include <math.h>

#define BB 64
#define SS 64
#define WW 12
#define SYM 128
#define HID 256
#define EE 64
#define RR 32
#define VV 32000

typedef unsigned long long u64;

__device__ __align__(16) float g_sent[BB*SS*SYM];
__device__ __align__(16) float g_qsum[BB*SYM];
__device__ __align__(16) float g_e1[BB*SS*EE];
__device__ __align__(16) float g_e2[BB*SS*EE];
__device__ __align__(16) float g_r1[BB*SS*RR];
__device__ __align__(16) float g_r2[BB*SS*RR];
__device__ __align__(16) float g_r3[BB*SS*RR];
__device__ __align__(16) float g_qe1[BB*EE];
__device__ __align__(16) float g_qe2[BB*EE];
__device__ __align__(16) float g_qr1[BB*RR];
__device__ __align__(16) float g_qr2[BB*RR];
__device__ __align__(16) float g_qr3[BB*RR];
__device__ __align__(16) float g_gram[(size_t)BB*9*SS*SS];   // raw grams
__device__ __align__(16) float g_coef[(size_t)BB*9*SS*SS];   // precomputed coefficient planes
__device__ __align__(16) float g_abc[(size_t)BB*3*SS*EE];
__device__ __align__(16) float g_isum[BB*EE];

__device__ __forceinline__ u64 fma2(u64 a, u64 b, u64 c) {
    u64 d;
    asm("fma.rn.f32x2 %0, %1, %2, %3;" : "=l"(d) : "l"(a), "l"(b), "l"(c));
    return d;
}
__device__ __forceinline__ float2 unpack2(u64 a) {
    float2 r;
    asm("mov.b64 {%0,%1}, %2;" : "=f"(r.x), "=f"(r.y) : "l"(a));
    return r;
}
__device__ __forceinline__ u64 pack2(float x, float y) {
    u64 r;
    asm("mov.b64 %0, {%1,%2};" : "=l"(r) : "f"(x), "f"(y));
    return r;
}
__device__ __forceinline__ float fast_tanh(float x) {
    float e = __expf(2.f * x);
    return 1.f - __fdividef(2.f, e + 1.f);
}

// ---------------- 1) embedding ----------------
__global__ void embed_kernel(const int* __restrict__ story, const int* __restrict__ query,
                             const float* __restrict__ WE, const float* __restrict__ PE) {
    int r = blockIdx.x;
    int e = threadIdx.x;
    const int* idx;
    float* dst;
    if (r < BB*SS) { idx = story + r*WW; dst = g_sent + r*SYM; }
    else           { int rb = r - BB*SS; idx = query + rb*WW; dst = g_qsum + rb*SYM; }
    float acc = 0.f;
#pragma unroll
    for (int w = 0; w < WW; ++w) {
        int t = __ldg(idx + w);
        acc = fmaf(WE[(size_t)t*SYM + e], PE[w*SYM + e], acc);
    }
    dst[e] = acc;
}

// ---------------- 2) fused 5-head MLP (R11 structure, fast_tanh) ----------------
#define XSTR 132
#define W1S 260
#define W2S64 68
#define W2S32 36
#define HSTR 260
#define WREG 4352
#define MLP_SMEM_FLOATS (32*XSTR + WREG + 32*HSTR)
__global__ void __launch_bounds__(128) mlp5_kernel(
    const float* __restrict__ Xs_story, const float* __restrict__ Xs_query,
    const float* __restrict__ ueW1, const float* __restrict__ ueb1,
    const float* __restrict__ ueW2, const float* __restrict__ ueb2,
    const float* __restrict__ urW1, const float* __restrict__ urb1,
    const float* __restrict__ urW2, const float* __restrict__ urb2,
    const float* __restrict__ ieW1, const float* __restrict__ ieb1,
    const float* __restrict__ ieW2, const float* __restrict__ ieb2,
    const float* __restrict__ irW1, const float* __restrict__ irb1,
    const float* __restrict__ irW2, const float* __restrict__ irb2,
    float* __restrict__ so0, float* __restrict__ so1,
    float* __restrict__ so2, float* __restrict__ so3, float* __restrict__ so4,
    float* __restrict__ qo0, float* __restrict__ qo1,
    float* __restrict__ qo2, float* __restrict__ qo3, float* __restrict__ qo4)
{
    extern __shared__ float smm[];
    float* Xs = smm;
    float* Ws = Xs + 32*XSTR;
    float* Hs = Ws + WREG;

    int h = blockIdx.y;
    bool is_q = (blockIdx.x >= BB*SS/32);
    const float* X = is_q ? Xs_query : Xs_story;
    int row0 = (is_q ? (blockIdx.x - BB*SS/32) : blockIdx.x) * 32;

    const float *eW1 = is_q ? ieW1 : ueW1, *eb1 = is_q ? ieb1 : ueb1;
    const float *eW2 = is_q ? ieW2 : ueW2, *eb2 = is_q ? ieb2 : ueb2;
    const float *rW1 = is_q ? irW1 : urW1, *rb1 = is_q ? irb1 : urb1;
    const float *rW2 = is_q ? irW2 : urW2, *rb2 = is_q ? irb2 : urb2;

    const float *W1, *b1, *W2, *b2;
    float* out;
    int Dout;
    if (h < 2) {
        W1 = eW1 + (size_t)h*SYM*HID; b1 = eb1 + h*HID;
        W2 = eW2 + (size_t)h*HID*EE;  b2 = eb2 + h*EE;
        out = h ? (is_q ? qo1 : so1) : (is_q ? qo0 : so0); Dout = EE;
    } else {
        int g = h - 2;
        W1 = rW1 + (size_t)g*SYM*HID; b1 = rb1 + g*HID;
        W2 = rW2 + (size_t)g*HID*RR;  b2 = rb2 + g*RR;
        out = (g == 0) ? (is_q ? qo2 : so2)
            : ((g == 1) ? (is_q ? qo3 : so3) : (is_q ? qo4 : so4));
        Dout = RR;
    }

    int tid = threadIdx.x;
    int ty = tid >> 4, tx = tid & 15;

    for (int idx = tid; idx < 32*32; idx += 128) {
        int r = idx >> 5, c4 = idx & 31;
        ((float4*)(Xs + r*XSTR))[c4] = ((const float4*)(X + (size_t)(row0 + r)*SYM))[c4];
    }

    u64 acc2[4][8];
    {
        const u64* bp = (const u64*)(b1 + tx*16);
#pragma unroll
        for (int c = 0; c < 8; ++c) {
            u64 bv = bp[c];
#pragma unroll
            for (int r = 0; r < 4; ++r) acc2[r][c] = bv;
        }
    }
    __syncthreads();

    for (int kk = 0; kk < 8; ++kk) {
        for (int idx = tid; idx < 16*64; idx += 128) {
            int r = idx >> 6, c4 = idx & 63;
            ((float4*)(Ws + r*W1S))[c4] = ((const float4*)(W1 + (size_t)(kk*16 + r)*HID))[c4];
        }
        __syncthreads();
#pragma unroll
        for (int k2 = 0; k2 < 8; ++k2) {
            u64 xx0[4], xx1[4];
#pragma unroll
            for (int r = 0; r < 4; ++r) {
                u64 xu = *(const u64*)(Xs + (ty*4 + r)*XSTR + kk*16 + k2*2);
                float2 xf = unpack2(xu);
                xx0[r] = pack2(xf.x, xf.x);
                xx1[r] = pack2(xf.y, xf.y);
            }
            const ulonglong2* w0p = (const ulonglong2*)(Ws + (k2*2    )*W1S + tx*16);
            const ulonglong2* w1p = (const ulonglong2*)(Ws + (k2*2 + 1)*W1S + tx*16);
#pragma unroll
            for (int q = 0; q < 4; ++q) {
                ulonglong2 w0 = w0p[q];
                ulonglong2 w1 = w1p[q];
#pragma unroll
                for (int r = 0; r < 4; ++r) {
                    acc2[r][2*q  ] = fma2(xx0[r], w0.x, acc2[r][2*q  ]);
                    acc2[r][2*q+1] = fma2(xx0[r], w0.y, acc2[r][2*q+1]);
                    acc2[r][2*q  ] = fma2(xx1[r], w1.x, acc2[r][2*q  ]);
                    acc2[r][2*q+1] = fma2(xx1[r], w1.y, acc2[r][2*q+1]);
                }
            }
        }
        __syncthreads();
    }

#pragma unroll
    for (int r = 0; r < 4; ++r)
#pragma unroll
        for (int c = 0; c < 8; ++c) {
            float2 v = unpack2(acc2[r][c]);
            *(u64*)(Hs + (ty*4 + r)*HSTR + tx*16 + 2*c) = pack2(fast_tanh(v.x), fast_tanh(v.y));
        }
    __syncthreads();

    if (Dout == EE) {
        const int st = W2S64;
        u64 oa[4][2];
        {
            const u64* bp = (const u64*)(b2 + tx*4);
            u64 b0 = bp[0], b1v = bp[1];
#pragma unroll
            for (int r = 0; r < 4; ++r) { oa[r][0] = b0; oa[r][1] = b1v; }
        }
        for (int kk = 0; kk < 4; ++kk) {
            for (int idx = tid; idx < 64*16; idx += 128) {
                int r = idx >> 4, c4 = idx & 15;
                ((float4*)(Ws + r*st))[c4] = ((const float4*)(W2 + (size_t)(kk*64 + r)*EE))[c4];
            }
            __syncthreads();
#pragma unroll
            for (int k2 = 0; k2 < 32; ++k2) {
                u64 hh0[4], hh1[4];
#pragma unroll
                for (int r = 0; r < 4; ++r) {
                    u64 hu = *(const u64*)(Hs + (ty*4 + r)*HSTR + kk*64 + k2*2);
                    float2 hf = unpack2(hu);
                    hh0[r] = pack2(hf.x, hf.x);
                    hh1[r] = pack2(hf.y, hf.y);
                }
                const u64* w0p = (const u64*)(Ws + (k2*2    )*st + tx*4);
                const u64* w1p = (const u64*)(Ws + (k2*2 + 1)*st + tx*4);
                u64 w00 = w0p[0], w01 = w0p[1], w10 = w1p[0], w11 = w1p[1];
#pragma unroll
                for (int r = 0; r < 4; ++r) {
                    oa[r][0] = fma2(hh0[r], w00, oa[r][0]);
                    oa[r][1] = fma2(hh0[r], w01, oa[r][1]);
                    oa[r][0] = fma2(hh1[r], w10, oa[r][0]);
                    oa[r][1] = fma2(hh1[r], w11, oa[r][1]);
                }
            }
            __syncthreads();
        }
#pragma unroll
        for (int r = 0; r < 4; ++r) {
            *(u64*)(out + (size_t)(row0 + ty*4 + r)*EE + tx*4    ) = oa[r][0];
            *(u64*)(out + (size_t)(row0 + ty*4 + r)*EE + tx*4 + 2) = oa[r][1];
        }
    } else {
        const int st = W2S32;
        u64 oa[4];
        {
            u64 b0 = *(const u64*)(b2 + tx*2);
#pragma unroll
            for (int r = 0; r < 4; ++r) oa[r] = b0;
        }
        for (int kk = 0; kk < 4; ++kk) {
            for (int idx = tid; idx < 64*8; idx += 128) {
                int r = idx >> 3, c4 = idx & 7;
                ((float4*)(Ws + r*st))[c4] = ((const float4*)(W2 + (size_t)(kk*64 + r)*RR))[c4];
            }
            __syncthreads();
#pragma unroll
            for (int k2 = 0; k2 < 32; ++k2) {
                u64 hh0[4], hh1[4];
#pragma unroll
                for (int r = 0; r < 4; ++r) {
                    u64 hu = *(const u64*)(Hs + (ty*4 + r)*HSTR + kk*64 + k2*2);
                    float2 hf = unpack2(hu);
                    hh0[r] = pack2(hf.x, hf.x);
                    hh1[r] = pack2(hf.y, hf.y);
                }
                u64 w0 = *(const u64*)(Ws + (k2*2    )*st + tx*2);
                u64 w1 = *(const u64*)(Ws + (k2*2 + 1)*st + tx*2);
#pragma unroll
                for (int r = 0; r < 4; ++r) {
                    oa[r] = fma2(hh0[r], w0, oa[r]);
                    oa[r] = fma2(hh1[r], w1, oa[r]);
                }
            }
            __syncthreads();
        }
#pragma unroll
        for (int r = 0; r < 4; ++r)
            *(u64*)(out + (size_t)(row0 + ty*4 + r)*RR + tx*2) = oa[r];
    }
}

// ---------------- 3a) Gram kernel (register-tiled, f32x2) ----------------
__global__ void __launch_bounds__(128) gram_kernel() {
    __shared__ float sX[64*66];
    __shared__ float sY[64*66];
    int b = blockIdx.x, w = blockIdx.y, tid = threadIdx.x;
    size_t off64 = (size_t)b*SS*EE;
    size_t off32 = (size_t)b*SS*RR;
    const float *X, *Y;
    int D, dsh;
    if (w == 0)      { X = g_e1 + off64; Y = g_e1 + off64; D = 64; dsh = 6; }
    else if (w == 1) { X = g_e1 + off64; Y = g_e2 + off64; D = 64; dsh = 6; }
    else if (w == 2) { X = g_e2 + off64; Y = g_e2 + off64; D = 64; dsh = 6; }
    else {
        int pq = w - 3;
        const float* rb[3] = { g_r1 + off32, g_r2 + off32, g_r3 + off32 };
        const int pi[6] = {0,0,0,1,1,2};
        const int qi[6] = {0,1,2,1,2,2};
        X = rb[pi[pq]]; Y = rb[qi[pq]]; D = 32; dsh = 5;
    }
    for (int idx = tid; idx < 64*D; idx += 128) {
        int row = idx >> dsh, d = idx & (D-1);
        sX[row*66 + d] = X[idx];
        sY[row*66 + d] = Y[idx];
    }
    __syncthreads();

    int ty = tid >> 3, tx = tid & 7;
    int s0 = ty * 4, t0 = tx * 8;
    u64 acc[4][8];
#pragma unroll
    for (int i = 0; i < 4; ++i)
#pragma unroll
        for (int j = 0; j < 8; ++j) acc[i][j] = 0ull;

    int DP = D >> 1;
#pragma unroll 4
    for (int dp = 0; dp < DP; ++dp) {
        u64 x2[4], y2[8];
#pragma unroll
        for (int i = 0; i < 4; ++i) x2[i] = *(const u64*)(sX + (s0+i)*66 + 2*dp);
#pragma unroll
        for (int j = 0; j < 8; ++j) y2[j] = *(const u64*)(sY + (t0+j)*66 + 2*dp);
#pragma unroll
        for (int i = 0; i < 4; ++i)
#pragma unroll
            for (int j = 0; j < 8; ++j)
                acc[i][j] = fma2(x2[i], y2[j], acc[i][j]);
    }

    float* out = g_gram + ((size_t)(b*9 + w) << 12);
#pragma unroll
    for (int i = 0; i < 4; ++i)
#pragma unroll
        for (int j = 0; j < 8; ++j) {
            float2 p = unpack2(acc[i][j]);
            out[(s0+i)*64 + (t0+j)] = p.x + p.y;
        }
}

// ---------------- 3b) coefficient kernel: smem-staged, conflict-free transpose ----------------
// coef plane w at (s,t): E[eP](s,t or t,s) * R[rP](s,t or t,s)
__global__ void __launch_bounds__(256) coef_kernel() {
    __shared__ float sGe[64*65];
    __shared__ float sGr[64*65];
    const int eP[9] = {0,0,1,0,0,1,1,1,2};
    const int eT[9] = {0,0,0,0,0,0,1,1,0};
    const int rP[9] = {3,4,5,4,6,7,5,7,8};
    const int rT[9] = {0,0,0,1,0,0,1,1,0};
    int b = blockIdx.x, w = blockIdx.y, tid = threadIdx.x;
    const float* G = g_gram + (size_t)b*9*4096;
    const float* Ge = G + eP[w]*4096;
    const float* Gr = G + rP[w]*4096;

    // coalesced stage into padded smem
    for (int i = tid; i < 4096; i += 256) {
        int s = i >> 6, t = i & 63;
        sGe[s*65 + t] = Ge[i];
        sGr[s*65 + t] = Gr[i];
    }
    __syncthreads();

    float* out = g_coef + ((size_t)(b*9 + w) << 12);
    bool et = eT[w], rt = rT[w];
    for (int i = tid; i < 4096; i += 256) {
        int s = i >> 6, t = i & 63;
        float ev = et ? sGe[t*65 + s] : sGe[s*65 + t];
        float rv = rt ? sGr[t*65 + s] : sGr[s*65 + t];
        out[i] = ev * rv;
    }
}

// ---------------- 3c) Gram-space scan, paired steps: grid (BB,2), block 256 ----------------
#define SL_SMEM_FLOATS (9*4096 + 5*2048 + 1536)
__global__ void __launch_bounds__(256) scanloop_kernel() {
    extern __shared__ float sm[];
    float* sCoef = sm;
    float* sAh   = sm + 9*4096;
    float* sBh   = sAh + 2048;
    float* sCh   = sBh + 2048;
    float* sE1h  = sCh + 2048;
    float* sE2h  = sE1h + 2048;
    float* sP    = sE2h + 2048;   // 6 x 256

    int b = blockIdx.x, by = blockIdx.y, tid = threadIdx.x;
    int g = tid >> 5, fl = tid & 31;

    {
        const float4* c4 = (const float4*)(g_coef + (size_t)b*9*4096);
        float4* s4 = (float4*)sCoef;
        for (int i = tid; i < 9216; i += 256) s4[i] = c4[i];
        for (int i = tid; i < 2048; i += 256) {
            int t = i >> 5, f2 = i & 31;
            sE1h[i] = g_e1[((size_t)(b*SS + t))*EE + (by << 5) + f2];
            sE2h[i] = g_e2[((size_t)(b*SS + t))*EE + (by << 5) + f2];
        }
    }
    __syncthreads();

    for (int s = 0; s < SS; s += 2) {
        int row0 = s << 6, row1 = (s + 1) << 6;
        float wa0=0.f, wb0=0.f, wc0=0.f, ma0=0.f, mb0=0.f, mc0=0.f, ba0=0.f, bb0=0.f, bc0=0.f;
        float wa1=0.f, wb1=0.f, wc1=0.f, ma1=0.f, mb1=0.f, mc1=0.f, ba1=0.f, bb1=0.f, bc1=0.f;
        for (int t = g; t < s; t += 8) {
            int tf = (t << 5) + fl;
            float at = sAh[tf], bt = sBh[tf], ct = sCh[tf];
            int s0t = row0 + t, s1t = row1 + t;
            wa0 = fmaf(sCoef[          s0t], at, wa0);
            wb0 = fmaf(sCoef[  4096 + s0t], bt, wb0);
            wc0 = fmaf(sCoef[2*4096 + s0t], ct, wc0);
            ma0 = fmaf(sCoef[3*4096 + s0t], at, ma0);
            mb0 = fmaf(sCoef[4*4096 + s0t], bt, mb0);
            mc0 = fmaf(sCoef[5*4096 + s0t], ct, mc0);
            ba0 = fmaf(sCoef[6*4096 + s0t], at, ba0);
            bb0 = fmaf(sCoef[7*4096 + s0t], bt, bb0);
            bc0 = fmaf(sCoef[8*4096 + s0t], ct, bc0);
            wa1 = fmaf(sCoef[          s1t], at, wa1);
            wb1 = fmaf(sCoef[  4096 + s1t], bt, wb1);
            wc1 = fmaf(sCoef[2*4096 + s1t], ct, wc1);
            ma1 = fmaf(sCoef[3*4096 + s1t], at, ma1);
            mb1 = fmaf(sCoef[4*4096 + s1t], bt, mb1);
            mc1 = fmaf(sCoef[5*4096 + s1t], ct, mc1);
            ba1 = fmaf(sCoef[6*4096 + s1t], at, ba1);
            bb1 = fmaf(sCoef[7*4096 + s1t], bt, bb1);
            bc1 = fmaf(sCoef[8*4096 + s1t], ct, bc1);
        }
        int pi = (g << 5) + fl;
        sP[         pi] = (wa0 + wb0) + wc0;
        sP[  256 +  pi] = (ma0 + mb0) + mc0;
        sP[2*256 +  pi] = (ba0 + bb0) + bc0;
        sP[3*256 +  pi] = (wa1 + wb1) + wc1;
        sP[4*256 +  pi] = (ma1 + mb1) + mc1;
        sP[5*256 +  pi] = (ba1 + bb1) + bc1;
        __syncthreads();
        if (tid < 32) {
            float w0 = 0.f, m0 = 0.f, bh0 = 0.f, w1 = 0.f, m1 = 0.f, bh1 = 0.f;
#pragma unroll
            for (int q = 0; q < 8; ++q) {
                int qi = (q << 5) + tid;
                w0  += sP[         qi];
                m0  += sP[  256 +  qi];
                bh0 += sP[2*256 +  qi];
                w1  += sP[3*256 +  qi];
                m1  += sP[4*256 +  qi];
                bh1 += sP[5*256 +  qi];
            }
            int rw0 = (s << 5) + tid;
            int rw1 = rw0 + 32;
            float a0 = sE2h[rw0] - w0;
            float b0 = w0 - m0;
            float c0 = sE1h[rw0] - bh0;
            sAh[rw0] = a0; sBh[rw0] = b0; sCh[rw0] = c0;
            int st = row1 + s;
            w1  += sCoef[          st]*a0 + sCoef[  4096 + st]*b0 + sCoef[2*4096 + st]*c0;
            m1  += sCoef[3*4096 + st]*a0 + sCoef[4*4096 + st]*b0 + sCoef[5*4096 + st]*c0;
            bh1 += sCoef[6*4096 + st]*a0 + sCoef[7*4096 + st]*b0 + sCoef[8*4096 + st]*c0;
            sAh[rw1] = sE2h[rw1] - w1;
            sBh[rw1] = w1 - m1;
            sCh[rw1] = sE1h[rw1] - bh1;
        }
        __syncthreads();
    }

    for (int i = tid; i < 2048; i += 256) {
        int t = i >> 5, f2 = i & 31;
        size_t base = ((size_t)(b*3)*SS + t)*EE + (by << 5) + f2;
        g_abc[base          ] = sAh[i];
        g_abc[base + SS*EE  ] = sBh[i];
        g_abc[base + 2*SS*EE] = sCh[i];
    }
}

// ---------------- 4) inference chain ----------------
#define IF_SMEM_FLOATS (3*4096 + 2*65*64 + 6*64 + 4 + 128)
__global__ void __launch_bounds__(128) infer_kernel(
    const float* __restrict__ qe1,
    const float* __restrict__ qr1, const float* __restrict__ qr2, const float* __restrict__ qr3,
    const float* __restrict__ ln_g, const float* __restrict__ ln_b)
{
    extern __shared__ float sm[];
    float* sA   = sm;
    float* sB   = sA + 4096;
    float* sC   = sB + 4096;
    float* sE1T = sC + 4096;
    float* sE2T = sE1T + 65*64;
    float* cur  = sE2T + 65*64;
    float* d1   = cur + 64;
    float* d2   = d1 + 64;
    float* ca   = d2 + 64;
    float* cb   = ca + 64;
    float* cc   = cb + 64;
    float* lnr  = cc + 64;
    float* sPar = lnr + 4;

    int b = blockIdx.x, tid = threadIdx.x;
    int g = tid >> 6, f = tid & 63;

    {
        const float4* a4 = (const float4*)(g_abc + (size_t)(b*3)*SS*EE);
        float4* s4 = (float4*)sA;
        for (int i = tid; i < 3*1024; i += 128) s4[i] = a4[i];
        for (int i = tid; i < 4096; i += 128) {
            int tt = i >> 6, ff = i & 63;
            sE1T[ff*65 + tt] = g_e1[((size_t)(b*SS + tt))*EE + ff];
            sE2T[ff*65 + tt] = g_e2[((size_t)(b*SS + tt))*EE + ff];
        }
    }
    if (tid < 64) cur[tid] = qe1[b*EE + tid];
    __syncthreads();

    float isum = 0.f;
    for (int p = 0; p < 3; ++p) {
        const float* qrp = (p == 0 ? qr1 : (p == 1 ? qr2 : qr3)) + b*RR;
        if (tid < 64) {
            int t = tid;
            float s1 = 0.f, s2 = 0.f;
            for (int f2 = 0; f2 < 64; ++f2) {
                float cv = cur[f2];
                s1 = fmaf(cv, sE1T[f2*65 + t], s1);
                s2 = fmaf(cv, sE2T[f2*65 + t], s2);
            }
            d1[t] = s1; d2[t] = s2;
        } else {
            int t = tid - 64;
            const float* r1p = g_r1 + ((size_t)(b*SS + t))*RR;
            const float* r2p = g_r2 + ((size_t)(b*SS + t))*RR;
            const float* r3p = g_r3 + ((size_t)(b*SS + t))*RR;
            float a1 = 0.f, a2 = 0.f, a3 = 0.f;
            for (int r = 0; r < RR; ++r) {
                float q = qrp[r];
                a1 = fmaf(q, r1p[r], a1);
                a2 = fmaf(q, r2p[r], a2);
                a3 = fmaf(q, r3p[r], a3);
            }
            ca[t] = a1; cb[t] = a2; cc[t] = a3;
        }
        __syncthreads();
        if (tid < 64) {
            int t = tid;
            ca[t] *= d1[t];
            cb[t] *= d1[t];
            cc[t] *= d2[t];
        }
        __syncthreads();
        {
            float acc = 0.f;
            for (int t = g; t < 64; t += 2) {
                int tf = (t << 6) + f;
                acc = fmaf(ca[t], sA[tf], fmaf(cb[t], sB[tf], fmaf(cc[t], sC[tf], acc)));
            }
            sPar[(g << 6) + f] = acc;
        }
        __syncthreads();
        if (g == 0) {
            float raw = sPar[f] + sPar[64 + f];
            float ssum = raw;
#pragma unroll
            for (int off = 16; off > 0; off >>= 1) ssum += __shfl_xor_sync(0xffffffffu, ssum, off);
            if ((f & 31) == 0) lnr[f >> 5] = ssum;
        }
        __syncthreads();
        if (g == 0) {
            float raw = sPar[f] + sPar[64 + f];
            float mean = (lnr[0] + lnr[1]) * (1.f/64.f);
            float d = raw - mean;
            float q = d * d;
#pragma unroll
            for (int off = 16; off > 0; off >>= 1) q += __shfl_xor_sync(0xffffffffu, q, off);
            if ((f & 31) == 0) lnr[2 + (f >> 5)] = q;
        }
        __syncthreads();
        if (g == 0) {
            float raw = sPar[f] + sPar[64 + f];
            float mean = (lnr[0] + lnr[1]) * (1.f/64.f);
            float var  = (lnr[2] + lnr[3]) * (1.f/64.f);
            float val = (raw - mean) * rsqrtf(var + 1e-5f) * ln_g[p*EE + f] + ln_b[p*EE + f];
            cur[f] = val;
            isum += val;
        }
        __syncthreads();
    }
    if (g == 0) g_isum[b*EE + f] = isum;
}

// ---------------- 5) output GEMM ----------------
__global__ void __launch_bounds__(128) outgemm_kernel(const float* __restrict__ Z,
                                                      float* __restrict__ out) {
    __shared__ float sI[16][64];
    int bx = blockIdx.x, by = blockIdx.y, tid = threadIdx.x;
    for (int idx = tid; idx < 1024; idx += 128)
        sI[idx >> 6][idx & 63] = g_isum[by*1024 + idx];
    __syncthreads();

    int v = bx*128 + tid;
    float acc[16];
#pragma unroll
    for (int i = 0; i < 16; ++i) acc[i] = 0.f;
#pragma unroll 4
    for (int e = 0; e < 64; ++e) {
        float z = __ldg(Z + (size_t)e*VV + v);
#pragma unroll
        for (int i = 0; i < 16; ++i)
            acc[i] = fmaf(sI[i][e], z, acc[i]);
    }
#pragma unroll
    for (int i = 0; i < 16; ++i)
        out[(size_t)(by*16 + i)*VV + v] = acc[i];
}

// ---------------- launch ----------------
extern "C" void kernel_launch(void* const* d_in, const int* in_sizes, int n_in,
                              void* d_out, int out_size) {
    const int*   story = (const int*)d_in[0];
    const int*   query = (const int*)d_in[1];
    const float* WE    = (const float*)d_in[2];
    const float* PE    = (const float*)d_in[3];
    const float* ue_W1 = (const float*)d_in[4];
    const float* ue_b1 = (const float*)d_in[5];
    const float* ue_W2 = (const float*)d_in[6];
    const float* ue_b2 = (const float*)d_in[7];
    const float* ur_W1 = (const float*)d_in[8];
    const float* ur_b1 = (const float*)d_in[9];
    const float* ur_W2 = (const float*)d_in[10];
    const float* ur_b2 = (const float*)d_in[11];
    const float* ie_W1 = (const float*)d_in[12];
    const float* ie_b1 = (const float*)d_in[13];
    const float* ie_W2 = (const float*)d_in[14];
    const float* ie_b2 = (const float*)d_in[15];
    const float* ir_W1 = (const float*)d_in[16];
    const float* ir_b1 = (const float*)d_in[17];
    const float* ir_W2 = (const float*)d_in[18];
    const float* ir_b2 = (const float*)d_in[19];
    const float* ln_g  = (const float*)d_in[20];
    const float* ln_b  = (const float*)d_in[21];
    const float* Z     = (const float*)d_in[22];
    float* out = (float*)d_out;

    const int MLP_SMEM = MLP_SMEM_FLOATS * (int)sizeof(float);
    const int SL_SMEM  = SL_SMEM_FLOATS * (int)sizeof(float);
    const int IF_SMEM  = IF_SMEM_FLOATS * (int)sizeof(float);
    cudaFuncSetAttribute(mlp5_kernel, cudaFuncAttributeMaxDynamicSharedMemorySize, MLP_SMEM);
    cudaFuncSetAttribute(scanloop_kernel, cudaFuncAttributeMaxDynamicSharedMemorySize, SL_SMEM);
    cudaFuncSetAttribute(infer_kernel, cudaFuncAttributeMaxDynamicSharedMemorySize, IF_SMEM);

    float *d_sent, *d_qsum, *d_e1, *d_e2, *d_r1, *d_r2, *d_r3;
    float *d_qe1, *d_qe2, *d_qr1, *d_qr2, *d_qr3;
    cudaGetSymbolAddress((void**)&d_sent, g_sent);
    cudaGetSymbolAddress((void**)&d_qsum, g_qsum);
    cudaGetSymbolAddress((void**)&d_e1, g_e1);
    cudaGetSymbolAddress((void**)&d_e2, g_e2);
    cudaGetSymbolAddress((void**)&d_r1, g_r1);
    cudaGetSymbolAddress((void**)&d_r2, g_r2);
    cudaGetSymbolAddress((void**)&d_r3, g_r3);
    cudaGetSymbolAddress((void**)&d_qe1, g_qe1);
    cudaGetSymbolAddress((void**)&d_qe2, g_qe2);
    cudaGetSymbolAddress((void**)&d_qr1, g_qr1);
    cudaGetSymbolAddress((void**)&d_qr2, g_qr2);
    cudaGetSymbolAddress((void**)&d_qr3, g_qr3);

    embed_kernel<<<BB*SS + BB, SYM>>>(story, query, WE, PE);

    mlp5_kernel<<<dim3(BB*SS/32 + 2, 5), 128, MLP_SMEM>>>(
        d_sent, d_qsum,
        ue_W1, ue_b1, ue_W2, ue_b2, ur_W1, ur_b1, ur_W2, ur_b2,
        ie_W1, ie_b1, ie_W2, ie_b2, ir_W1, ir_b1, ir_W2, ir_b2,
        d_e1, d_e2, d_r1, d_r2, d_r3,
        d_qe1, d_qe2, d_qr1, d_qr2, d_qr3);

    gram_kernel<<<dim3(BB, 9), 128>>>();
    coef_kernel<<<dim3(BB, 9), 256>>>();
    scanloop_kernel<<<dim3(BB, 2), 256, SL_SMEM>>>();
    infer_kernel<<<BB, 128, IF_SMEM>>>(d_qe1, d_qr1, d_qr2, d_qr3, ln_g, ln_b);
    outgemm_kernel<<<dim3(VV/128, BB/16), 128>>>(Z, out);
}

// round 17
// speedup vs baseline: 1.1056x; 1.0210x over previous
#include <cuda_runtime.h>
#include <cuda_bf16.h>
#include <math.h>

#define BB 64
#define SS 64
#define WW 12
#define SYM 128
#define HID 256
#define EE 64
#define RR 32
#define VV 32000

typedef unsigned long long u64;

__device__ __align__(16) float g_sent[BB*SS*SYM];
__device__ __align__(16) float g_qsum[BB*SYM];
__device__ __align__(16) float g_e1[BB*SS*EE];
__device__ __align__(16) float g_e2[BB*SS*EE];
__device__ __align__(16) float g_r1[BB*SS*RR];
__device__ __align__(16) float g_r2[BB*SS*RR];
__device__ __align__(16) float g_r3[BB*SS*RR];
__device__ __align__(16) float g_qe1[BB*EE];
__device__ __align__(16) float g_qe2[BB*EE];
__device__ __align__(16) float g_qr1[BB*RR];
__device__ __align__(16) float g_qr2[BB*RR];
__device__ __align__(16) float g_qr3[BB*RR];
__device__ __align__(16) float g_gram[(size_t)BB*9*SS*SS];   // raw grams
__device__ __align__(16) float g_coef[(size_t)BB*9*SS*SS];   // precomputed coefficient planes
__device__ __align__(16) float g_abc[(size_t)BB*3*SS*EE];
__device__ __align__(16) float g_isum[BB*EE];

__device__ __forceinline__ u64 fma2(u64 a, u64 b, u64 c) {
    u64 d;
    asm("fma.rn.f32x2 %0, %1, %2, %3;" : "=l"(d) : "l"(a), "l"(b), "l"(c));
    return d;
}
__device__ __forceinline__ float2 unpack2(u64 a) {
    float2 r;
    asm("mov.b64 {%0,%1}, %2;" : "=f"(r.x), "=f"(r.y) : "l"(a));
    return r;
}
__device__ __forceinline__ u64 pack2(float x, float y) {
    u64 r;
    asm("mov.b64 %0, {%1,%2};" : "=l"(r) : "f"(x), "f"(y));
    return r;
}
__device__ __forceinline__ float fast_tanh(float x) {
    float e = __expf(2.f * x);
    return 1.f - __fdividef(2.f, e + 1.f);
}

// ---------------- 1) embedding ----------------
__global__ void embed_kernel(const int* __restrict__ story, const int* __restrict__ query,
                             const float* __restrict__ WE, const float* __restrict__ PE) {
    int r = blockIdx.x;
    int e = threadIdx.x;
    const int* idx;
    float* dst;
    if (r < BB*SS) { idx = story + r*WW; dst = g_sent + r*SYM; }
    else           { int rb = r - BB*SS; idx = query + rb*WW; dst = g_qsum + rb*SYM; }
    float acc = 0.f;
#pragma unroll
    for (int w = 0; w < WW; ++w) {
        int t = __ldg(idx + w);
        acc = fmaf(WE[(size_t)t*SYM + e], PE[w*SYM + e], acc);
    }
    dst[e] = acc;
}

// ---------------- 2) fused 5-head MLP: reg-prefetch pipeline, same smem ----------------
#define XSTR 132
#define W1S 260
#define W2S64 68
#define W2S32 36
#define HSTR 260
#define WREG 4352
#define MLP_SMEM_FLOATS (32*XSTR + WREG + 32*HSTR)
__global__ void __launch_bounds__(128) mlp5_kernel(
    const float* __restrict__ Xs_story, const float* __restrict__ Xs_query,
    const float* __restrict__ ueW1, const float* __restrict__ ueb1,
    const float* __restrict__ ueW2, const float* __restrict__ ueb2,
    const float* __restrict__ urW1, const float* __restrict__ urb1,
    const float* __restrict__ urW2, const float* __restrict__ urb2,
    const float* __restrict__ ieW1, const float* __restrict__ ieb1,
    const float* __restrict__ ieW2, const float* __restrict__ ieb2,
    const float* __restrict__ irW1, const float* __restrict__ irb1,
    const float* __restrict__ irW2, const float* __restrict__ irb2,
    float* __restrict__ so0, float* __restrict__ so1,
    float* __restrict__ so2, float* __restrict__ so3, float* __restrict__ so4,
    float* __restrict__ qo0, float* __restrict__ qo1,
    float* __restrict__ qo2, float* __restrict__ qo3, float* __restrict__ qo4)
{
    extern __shared__ float smm[];
    float* Xs = smm;
    float* Ws = Xs + 32*XSTR;
    float* Hs = Ws + WREG;

    int h = blockIdx.y;
    bool is_q = (blockIdx.x >= BB*SS/32);
    const float* X = is_q ? Xs_query : Xs_story;
    int row0 = (is_q ? (blockIdx.x - BB*SS/32) : blockIdx.x) * 32;

    const float *eW1 = is_q ? ieW1 : ueW1, *eb1 = is_q ? ieb1 : ueb1;
    const float *eW2 = is_q ? ieW2 : ueW2, *eb2 = is_q ? ieb2 : ueb2;
    const float *rW1 = is_q ? irW1 : urW1, *rb1 = is_q ? irb1 : urb1;
    const float *rW2 = is_q ? irW2 : urW2, *rb2 = is_q ? irb2 : urb2;

    const float *W1, *b1, *W2, *b2;
    float* out;
    int Dout;
    if (h < 2) {
        W1 = eW1 + (size_t)h*SYM*HID; b1 = eb1 + h*HID;
        W2 = eW2 + (size_t)h*HID*EE;  b2 = eb2 + h*EE;
        out = h ? (is_q ? qo1 : so1) : (is_q ? qo0 : so0); Dout = EE;
    } else {
        int g = h - 2;
        W1 = rW1 + (size_t)g*SYM*HID; b1 = rb1 + g*HID;
        W2 = rW2 + (size_t)g*HID*RR;  b2 = rb2 + g*RR;
        out = (g == 0) ? (is_q ? qo2 : so2)
            : ((g == 1) ? (is_q ? qo3 : so3) : (is_q ? qo4 : so4));
        Dout = RR;
    }

    int tid = threadIdx.x;
    int ty = tid >> 4, tx = tid & 15;

    // stage X tile
    for (int idx = tid; idx < 32*32; idx += 128) {
        int r = idx >> 5, c4 = idx & 31;
        ((float4*)(Xs + r*XSTR))[c4] = ((const float4*)(X + (size_t)(row0 + r)*SYM))[c4];
    }

    // ---- layer 1, reg-prefetch pipeline ----
    u64 acc2[4][8];
    {
        const u64* bp = (const u64*)(b1 + tx*16);
#pragma unroll
        for (int c = 0; c < 8; ++c) {
            u64 bv = bp[c];
#pragma unroll
            for (int r = 0; r < 4; ++r) acc2[r][c] = bv;
        }
    }

    float4 wreg[8];
    {
        const float4* src = (const float4*)W1;
#pragma unroll
        for (int i = 0; i < 8; ++i) wreg[i] = src[i*128 + tid];
    }

    for (int kk = 0; kk < 8; ++kk) {
        // store current chunk regs -> smem
#pragma unroll
        for (int i = 0; i < 8; ++i) {
            int id = i*128 + tid;
            int r = id >> 6, c4 = id & 63;
            ((float4*)(Ws + r*W1S))[c4] = wreg[i];
        }
        __syncthreads();
        // issue next chunk LDG before compute (latency hidden by compute)
        if (kk < 7) {
            const float4* src = (const float4*)(W1 + (size_t)(kk+1)*16*HID);
#pragma unroll
            for (int i = 0; i < 8; ++i) wreg[i] = src[i*128 + tid];
        }
#pragma unroll
        for (int k2 = 0; k2 < 8; ++k2) {
            u64 xx0[4], xx1[4];
#pragma unroll
            for (int r = 0; r < 4; ++r) {
                u64 xu = *(const u64*)(Xs + (ty*4 + r)*XSTR + kk*16 + k2*2);
                float2 xf = unpack2(xu);
                xx0[r] = pack2(xf.x, xf.x);
                xx1[r] = pack2(xf.y, xf.y);
            }
            const ulonglong2* w0p = (const ulonglong2*)(Ws + (k2*2    )*W1S + tx*16);
            const ulonglong2* w1p = (const ulonglong2*)(Ws + (k2*2 + 1)*W1S + tx*16);
#pragma unroll
            for (int q = 0; q < 4; ++q) {
                ulonglong2 w0 = w0p[q];
                ulonglong2 w1 = w1p[q];
#pragma unroll
                for (int r = 0; r < 4; ++r) {
                    acc2[r][2*q  ] = fma2(xx0[r], w0.x, acc2[r][2*q  ]);
                    acc2[r][2*q+1] = fma2(xx0[r], w0.y, acc2[r][2*q+1]);
                    acc2[r][2*q  ] = fma2(xx1[r], w1.x, acc2[r][2*q  ]);
                    acc2[r][2*q+1] = fma2(xx1[r], w1.y, acc2[r][2*q+1]);
                }
            }
        }
        __syncthreads();
    }

#pragma unroll
    for (int r = 0; r < 4; ++r)
#pragma unroll
        for (int c = 0; c < 8; ++c) {
            float2 v = unpack2(acc2[r][c]);
            *(u64*)(Hs + (ty*4 + r)*HSTR + tx*16 + 2*c) = pack2(fast_tanh(v.x), fast_tanh(v.y));
        }
    __syncthreads();

    // ---- layer 2, reg-prefetch pipeline ----
    if (Dout == EE) {
        const int st = W2S64;
        u64 oa[4][2];
        {
            const u64* bp = (const u64*)(b2 + tx*4);
            u64 b0 = bp[0], b1v = bp[1];
#pragma unroll
            for (int r = 0; r < 4; ++r) { oa[r][0] = b0; oa[r][1] = b1v; }
        }
        float4 w2reg[8];
        {
            const float4* src = (const float4*)W2;
#pragma unroll
            for (int i = 0; i < 8; ++i) w2reg[i] = src[i*128 + tid];
        }
        for (int kk = 0; kk < 4; ++kk) {
#pragma unroll
            for (int i = 0; i < 8; ++i) {
                int id = i*128 + tid;
                int r = id >> 4, c4 = id & 15;
                ((float4*)(Ws + r*st))[c4] = w2reg[i];
            }
            __syncthreads();
            if (kk < 3) {
                const float4* src = (const float4*)(W2 + (size_t)(kk+1)*64*EE);
#pragma unroll
                for (int i = 0; i < 8; ++i) w2reg[i] = src[i*128 + tid];
            }
#pragma unroll
            for (int k2 = 0; k2 < 32; ++k2) {
                u64 hh0[4], hh1[4];
#pragma unroll
                for (int r = 0; r < 4; ++r) {
                    u64 hu = *(const u64*)(Hs + (ty*4 + r)*HSTR + kk*64 + k2*2);
                    float2 hf = unpack2(hu);
                    hh0[r] = pack2(hf.x, hf.x);
                    hh1[r] = pack2(hf.y, hf.y);
                }
                const u64* w0p = (const u64*)(Ws + (k2*2    )*st + tx*4);
                const u64* w1p = (const u64*)(Ws + (k2*2 + 1)*st + tx*4);
                u64 w00 = w0p[0], w01 = w0p[1], w10 = w1p[0], w11 = w1p[1];
#pragma unroll
                for (int r = 0; r < 4; ++r) {
                    oa[r][0] = fma2(hh0[r], w00, oa[r][0]);
                    oa[r][1] = fma2(hh0[r], w01, oa[r][1]);
                    oa[r][0] = fma2(hh1[r], w10, oa[r][0]);
                    oa[r][1] = fma2(hh1[r], w11, oa[r][1]);
                }
            }
            __syncthreads();
        }
#pragma unroll
        for (int r = 0; r < 4; ++r) {
            *(u64*)(out + (size_t)(row0 + ty*4 + r)*EE + tx*4    ) = oa[r][0];
            *(u64*)(out + (size_t)(row0 + ty*4 + r)*EE + tx*4 + 2) = oa[r][1];
        }
    } else {
        const int st = W2S32;
        u64 oa[4];
        {
            u64 b0 = *(const u64*)(b2 + tx*2);
#pragma unroll
            for (int r = 0; r < 4; ++r) oa[r] = b0;
        }
        float4 w2reg[4];
        {
            const float4* src = (const float4*)W2;
#pragma unroll
            for (int i = 0; i < 4; ++i) w2reg[i] = src[i*128 + tid];
        }
        for (int kk = 0; kk < 4; ++kk) {
#pragma unroll
            for (int i = 0; i < 4; ++i) {
                int id = i*128 + tid;
                int r = id >> 3, c4 = id & 7;
                ((float4*)(Ws + r*st))[c4] = w2reg[i];
            }
            __syncthreads();
            if (kk < 3) {
                const float4* src = (const float4*)(W2 + (size_t)(kk+1)*64*RR);
#pragma unroll
                for (int i = 0; i < 4; ++i) w2reg[i] = src[i*128 + tid];
            }
#pragma unroll
            for (int k2 = 0; k2 < 32; ++k2) {
                u64 hh0[4], hh1[4];
#pragma unroll
                for (int r = 0; r < 4; ++r) {
                    u64 hu = *(const u64*)(Hs + (ty*4 + r)*HSTR + kk*64 + k2*2);
                    float2 hf = unpack2(hu);
                    hh0[r] = pack2(hf.x, hf.x);
                    hh1[r] = pack2(hf.y, hf.y);
                }
                u64 w0 = *(const u64*)(Ws + (k2*2    )*st + tx*2);
                u64 w1 = *(const u64*)(Ws + (k2*2 + 1)*st + tx*2);
#pragma unroll
                for (int r = 0; r < 4; ++r) {
                    oa[r] = fma2(hh0[r], w0, oa[r]);
                    oa[r] = fma2(hh1[r], w1, oa[r]);
                }
            }
            __syncthreads();
        }
#pragma unroll
        for (int r = 0; r < 4; ++r)
            *(u64*)(out + (size_t)(row0 + ty*4 + r)*RR + tx*2) = oa[r];
    }
}

// ---------------- 3a) Gram kernel (register-tiled, f32x2) ----------------
__global__ void __launch_bounds__(128) gram_kernel() {
    __shared__ float sX[64*66];
    __shared__ float sY[64*66];
    int b = blockIdx.x, w = blockIdx.y, tid = threadIdx.x;
    size_t off64 = (size_t)b*SS*EE;
    size_t off32 = (size_t)b*SS*RR;
    const float *X, *Y;
    int D, dsh;
    if (w == 0)      { X = g_e1 + off64; Y = g_e1 + off64; D = 64; dsh = 6; }
    else if (w == 1) { X = g_e1 + off64; Y = g_e2 + off64; D = 64; dsh = 6; }
    else if (w == 2) { X = g_e2 + off64; Y = g_e2 + off64; D = 64; dsh = 6; }
    else {
        int pq = w - 3;
        const float* rb[3] = { g_r1 + off32, g_r2 + off32, g_r3 + off32 };
        const int pi[6] = {0,0,0,1,1,2};
        const int qi[6] = {0,1,2,1,2,2};
        X = rb[pi[pq]]; Y = rb[qi[pq]]; D = 32; dsh = 5;
    }
    for (int idx = tid; idx < 64*D; idx += 128) {
        int row = idx >> dsh, d = idx & (D-1);
        sX[row*66 + d] = X[idx];
        sY[row*66 + d] = Y[idx];
    }
    __syncthreads();

    int ty = tid >> 3, tx = tid & 7;
    int s0 = ty * 4, t0 = tx * 8;
    u64 acc[4][8];
#pragma unroll
    for (int i = 0; i < 4; ++i)
#pragma unroll
        for (int j = 0; j < 8; ++j) acc[i][j] = 0ull;

    int DP = D >> 1;
#pragma unroll 4
    for (int dp = 0; dp < DP; ++dp) {
        u64 x2[4], y2[8];
#pragma unroll
        for (int i = 0; i < 4; ++i) x2[i] = *(const u64*)(sX + (s0+i)*66 + 2*dp);
#pragma unroll
        for (int j = 0; j < 8; ++j) y2[j] = *(const u64*)(sY + (t0+j)*66 + 2*dp);
#pragma unroll
        for (int i = 0; i < 4; ++i)
#pragma unroll
            for (int j = 0; j < 8; ++j)
                acc[i][j] = fma2(x2[i], y2[j], acc[i][j]);
    }

    float* out = g_gram + ((size_t)(b*9 + w) << 12);
#pragma unroll
    for (int i = 0; i < 4; ++i)
#pragma unroll
        for (int j = 0; j < 8; ++j) {
            float2 p = unpack2(acc[i][j]);
            out[(s0+i)*64 + (t0+j)] = p.x + p.y;
        }
}

// ---------------- 3b) coefficient kernel: smem-staged, conflict-free transpose ----------------
__global__ void __launch_bounds__(256) coef_kernel() {
    __shared__ float sGe[64*65];
    __shared__ float sGr[64*65];
    const int eP[9] = {0,0,1,0,0,1,1,1,2};
    const int eT[9] = {0,0,0,0,0,0,1,1,0};
    const int rP[9] = {3,4,5,4,6,7,5,7,8};
    const int rT[9] = {0,0,0,1,0,0,1,1,0};
    int b = blockIdx.x, w = blockIdx.y, tid = threadIdx.x;
    const float* G = g_gram + (size_t)b*9*4096;
    const float* Ge = G + eP[w]*4096;
    const float* Gr = G + rP[w]*4096;

    for (int i = tid; i < 4096; i += 256) {
        int s = i >> 6, t = i & 63;
        sGe[s*65 + t] = Ge[i];
        sGr[s*65 + t] = Gr[i];
    }
    __syncthreads();

    float* out = g_coef + ((size_t)(b*9 + w) << 12);
    bool et = eT[w], rt = rT[w];
    for (int i = tid; i < 4096; i += 256) {
        int s = i >> 6, t = i & 63;
        float ev = et ? sGe[t*65 + s] : sGe[s*65 + t];
        float rv = rt ? sGr[t*65 + s] : sGr[s*65 + t];
        out[i] = ev * rv;
    }
}

// ---------------- 3c) Gram-space scan, paired steps: grid (BB,2), block 256 ----------------
#define SL_SMEM_FLOATS (9*4096 + 5*2048 + 1536)
__global__ void __launch_bounds__(256) scanloop_kernel() {
    extern __shared__ float sm[];
    float* sCoef = sm;
    float* sAh   = sm + 9*4096;
    float* sBh   = sAh + 2048;
    float* sCh   = sBh + 2048;
    float* sE1h  = sCh + 2048;
    float* sE2h  = sE1h + 2048;
    float* sP    = sE2h + 2048;   // 6 x 256

    int b = blockIdx.x, by = blockIdx.y, tid = threadIdx.x;
    int g = tid >> 5, fl = tid & 31;

    {
        const float4* c4 = (const float4*)(g_coef + (size_t)b*9*4096);
        float4* s4 = (float4*)sCoef;
        for (int i = tid; i < 9216; i += 256) s4[i] = c4[i];
        for (int i = tid; i < 2048; i += 256) {
            int t = i >> 5, f2 = i & 31;
            sE1h[i] = g_e1[((size_t)(b*SS + t))*EE + (by << 5) + f2];
            sE2h[i] = g_e2[((size_t)(b*SS + t))*EE + (by << 5) + f2];
        }
    }
    __syncthreads();

    for (int s = 0; s < SS; s += 2) {
        int row0 = s << 6, row1 = (s + 1) << 6;
        float wa0=0.f, wb0=0.f, wc0=0.f, ma0=0.f, mb0=0.f, mc0=0.f, ba0=0.f, bb0=0.f, bc0=0.f;
        float wa1=0.f, wb1=0.f, wc1=0.f, ma1=0.f, mb1=0.f, mc1=0.f, ba1=0.f, bb1=0.f, bc1=0.f;
        for (int t = g; t < s; t += 8) {
            int tf = (t << 5) + fl;
            float at = sAh[tf], bt = sBh[tf], ct = sCh[tf];
            int s0t = row0 + t, s1t = row1 + t;
            wa0 = fmaf(sCoef[          s0t], at, wa0);
            wb0 = fmaf(sCoef[  4096 + s0t], bt, wb0);
            wc0 = fmaf(sCoef[2*4096 + s0t], ct, wc0);
            ma0 = fmaf(sCoef[3*4096 + s0t], at, ma0);
            mb0 = fmaf(sCoef[4*4096 + s0t], bt, mb0);
            mc0 = fmaf(sCoef[5*4096 + s0t], ct, mc0);
            ba0 = fmaf(sCoef[6*4096 + s0t], at, ba0);
            bb0 = fmaf(sCoef[7*4096 + s0t], bt, bb0);
            bc0 = fmaf(sCoef[8*4096 + s0t], ct, bc0);
            wa1 = fmaf(sCoef[          s1t], at, wa1);
            wb1 = fmaf(sCoef[  4096 + s1t], bt, wb1);
            wc1 = fmaf(sCoef[2*4096 + s1t], ct, wc1);
            ma1 = fmaf(sCoef[3*4096 + s1t], at, ma1);
            mb1 = fmaf(sCoef[4*4096 + s1t], bt, mb1);
            mc1 = fmaf(sCoef[5*4096 + s1t], ct, mc1);
            ba1 = fmaf(sCoef[6*4096 + s1t], at, ba1);
            bb1 = fmaf(sCoef[7*4096 + s1t], bt, bb1);
            bc1 = fmaf(sCoef[8*4096 + s1t], ct, bc1);
        }
        int pi = (g << 5) + fl;
        sP[         pi] = (wa0 + wb0) + wc0;
        sP[  256 +  pi] = (ma0 + mb0) + mc0;
        sP[2*256 +  pi] = (ba0 + bb0) + bc0;
        sP[3*256 +  pi] = (wa1 + wb1) + wc1;
        sP[4*256 +  pi] = (ma1 + mb1) + mc1;
        sP[5*256 +  pi] = (ba1 + bb1) + bc1;
        __syncthreads();
        if (tid < 32) {
            float w0 = 0.f, m0 = 0.f, bh0 = 0.f, w1 = 0.f, m1 = 0.f, bh1 = 0.f;
#pragma unroll
            for (int q = 0; q < 8; ++q) {
                int qi = (q << 5) + tid;
                w0  += sP[         qi];
                m0  += sP[  256 +  qi];
                bh0 += sP[2*256 +  qi];
                w1  += sP[3*256 +  qi];
                m1  += sP[4*256 +  qi];
                bh1 += sP[5*256 +  qi];
            }
            int rw0 = (s << 5) + tid;
            int rw1 = rw0 + 32;
            float a0 = sE2h[rw0] - w0;
            float b0 = w0 - m0;
            float c0 = sE1h[rw0] - bh0;
            sAh[rw0] = a0; sBh[rw0] = b0; sCh[rw0] = c0;
            int st = row1 + s;
            w1  += sCoef[          st]*a0 + sCoef[  4096 + st]*b0 + sCoef[2*4096 + st]*c0;
            m1  += sCoef[3*4096 + st]*a0 + sCoef[4*4096 + st]*b0 + sCoef[5*4096 + st]*c0;
            bh1 += sCoef[6*4096 + st]*a0 + sCoef[7*4096 + st]*b0 + sCoef[8*4096 + st]*c0;
            sAh[rw1] = sE2h[rw1] - w1;
            sBh[rw1] = w1 - m1;
            sCh[rw1] = sE1h[rw1] - bh1;
        }
        __syncthreads();
    }

    for (int i = tid; i < 2048; i += 256) {
        int t = i >> 5, f2 = i & 31;
        size_t base = ((size_t)(b*3)*SS + t)*EE + (by << 5) + f2;
        g_abc[base          ] = sAh[i];
        g_abc[base + SS*EE  ] = sBh[i];
        g_abc[base + 2*SS*EE] = sCh[i];
    }
}

// ---------------- 4) inference chain ----------------
#define IF_SMEM_FLOATS (3*4096 + 2*65*64 + 6*64 + 4 + 128)
__global__ void __launch_bounds__(128) infer_kernel(
    const float* __restrict__ qe1,
    const float* __restrict__ qr1, const float* __restrict__ qr2, const float* __restrict__ qr3,
    const float* __restrict__ ln_g, const float* __restrict__ ln_b)
{
    extern __shared__ float sm[];
    float* sA   = sm;
    float* sB   = sA + 4096;
    float* sC   = sB + 4096;
    float* sE1T = sC + 4096;
    float* sE2T = sE1T + 65*64;
    float* cur  = sE2T + 65*64;
    float* d1   = cur + 64;
    float* d2   = d1 + 64;
    float* ca   = d2 + 64;
    float* cb   = ca + 64;
    float* cc   = cb + 64;
    float* lnr  = cc + 64;
    float* sPar = lnr + 4;

    int b = blockIdx.x, tid = threadIdx.x;
    int g = tid >> 6, f = tid & 63;

    {
        const float4* a4 = (const float4*)(g_abc + (size_t)(b*3)*SS*EE);
        float4* s4 = (float4*)sA;
        for (int i = tid; i < 3*1024; i += 128) s4[i] = a4[i];
        for (int i = tid; i < 4096; i += 128) {
            int tt = i >> 6, ff = i & 63;
            sE1T[ff*65 + tt] = g_e1[((size_t)(b*SS + tt))*EE + ff];
            sE2T[ff*65 + tt] = g_e2[((size_t)(b*SS + tt))*EE + ff];
        }
    }
    if (tid < 64) cur[tid] = qe1[b*EE + tid];
    __syncthreads();

    float isum = 0.f;
    for (int p = 0; p < 3; ++p) {
        const float* qrp = (p == 0 ? qr1 : (p == 1 ? qr2 : qr3)) + b*RR;
        if (tid < 64) {
            int t = tid;
            float s1 = 0.f, s2 = 0.f;
            for (int f2 = 0; f2 < 64; ++f2) {
                float cv = cur[f2];
                s1 = fmaf(cv, sE1T[f2*65 + t], s1);
                s2 = fmaf(cv, sE2T[f2*65 + t], s2);
            }
            d1[t] = s1; d2[t] = s2;
        } else {
            int t = tid - 64;
            const float* r1p = g_r1 + ((size_t)(b*SS + t))*RR;
            const float* r2p = g_r2 + ((size_t)(b*SS + t))*RR;
            const float* r3p = g_r3 + ((size_t)(b*SS + t))*RR;
            float a1 = 0.f, a2 = 0.f, a3 = 0.f;
            for (int r = 0; r < RR; ++r) {
                float q = qrp[r];
                a1 = fmaf(q, r1p[r], a1);
                a2 = fmaf(q, r2p[r], a2);
                a3 = fmaf(q, r3p[r], a3);
            }
            ca[t] = a1; cb[t] = a2; cc[t] = a3;
        }
        __syncthreads();
        if (tid < 64) {
            int t = tid;
            ca[t] *= d1[t];
            cb[t] *= d1[t];
            cc[t] *= d2[t];
        }
        __syncthreads();
        {
            float acc = 0.f;
            for (int t = g; t < 64; t += 2) {
                int tf = (t << 6) + f;
                acc = fmaf(ca[t], sA[tf], fmaf(cb[t], sB[tf], fmaf(cc[t], sC[tf], acc)));
            }
            sPar[(g << 6) + f] = acc;
        }
        __syncthreads();
        if (g == 0) {
            float raw = sPar[f] + sPar[64 + f];
            float ssum = raw;
#pragma unroll
            for (int off = 16; off > 0; off >>= 1) ssum += __shfl_xor_sync(0xffffffffu, ssum, off);
            if ((f & 31) == 0) lnr[f >> 5] = ssum;
        }
        __syncthreads();
        if (g == 0) {
            float raw = sPar[f] + sPar[64 + f];
            float mean = (lnr[0] + lnr[1]) * (1.f/64.f);
            float d = raw - mean;
            float q = d * d;
#pragma unroll
            for (int off = 16; off > 0; off >>= 1) q += __shfl_xor_sync(0xffffffffu, q, off);
            if ((f & 31) == 0) lnr[2 + (f >> 5)] = q;
        }
        __syncthreads();
        if (g == 0) {
            float raw = sPar[f] + sPar[64 + f];
            float mean = (lnr[0] + lnr[1]) * (1.f/64.f);
            float var  = (lnr[2] + lnr[3]) * (1.f/64.f);
            float val = (raw - mean) * rsqrtf(var + 1e-5f) * ln_g[p*EE + f] + ln_b[p*EE + f];
            cur[f] = val;
            isum += val;
        }
        __syncthreads();
    }
    if (g == 0) g_isum[b*EE + f] = isum;
}

// ---------------- 5) output GEMM ----------------
__global__ void __launch_bounds__(128) outgemm_kernel(const float* __restrict__ Z,
                                                      float* __restrict__ out) {
    __shared__ float sI[16][64];
    int bx = blockIdx.x, by = blockIdx.y, tid = threadIdx.x;
    for (int idx = tid; idx < 1024; idx += 128)
        sI[idx >> 6][idx & 63] = g_isum[by*1024 + idx];
    __syncthreads();

    int v = bx*128 + tid;
    float acc[16];
#pragma unroll
    for (int i = 0; i < 16; ++i) acc[i] = 0.f;
#pragma unroll 4
    for (int e = 0; e < 64; ++e) {
        float z = __ldg(Z + (size_t)e*VV + v);
#pragma unroll
        for (int i = 0; i < 16; ++i)
            acc[i] = fmaf(sI[i][e], z, acc[i]);
    }
#pragma unroll
    for (int i = 0; i < 16; ++i)
        out[(size_t)(by*16 + i)*VV + v] = acc[i];
}

// ---------------- launch ----------------
extern "C" void kernel_launch(void* const* d_in, const int* in_sizes, int n_in,
                              void* d_out, int out_size) {
    const int*   story = (const int*)d_in[0];
    const int*   query = (const int*)d_in[1];
    const float* WE    = (const float*)d_in[2];
    const float* PE    = (const float*)d_in[3];
    const float* ue_W1 = (const float*)d_in[4];
    const float* ue_b1 = (const float*)d_in[5];
    const float* ue_W2 = (const float*)d_in[6];
    const float* ue_b2 = (const float*)d_in[7];
    const float* ur_W1 = (const float*)d_in[8];
    const float* ur_b1 = (const float*)d_in[9];
    const float* ur_W2 = (const float*)d_in[10];
    const float* ur_b2 = (const float*)d_in[11];
    const float* ie_W1 = (const float*)d_in[12];
    const float* ie_b1 = (const float*)d_in[13];
    const float* ie_W2 = (const float*)d_in[14];
    const float* ie_b2 = (const float*)d_in[15];
    const float* ir_W1 = (const float*)d_in[16];
    const float* ir_b1 = (const float*)d_in[17];
    const float* ir_W2 = (const float*)d_in[18];
    const float* ir_b2 = (const float*)d_in[19];
    const float* ln_g  = (const float*)d_in[20];
    const float* ln_b  = (const float*)d_in[21];
    const float* Z     = (const float*)d_in[22];
    float* out = (float*)d_out;

    const int MLP_SMEM = MLP_SMEM_FLOATS * (int)sizeof(float);
    const int SL_SMEM  = SL_SMEM_FLOATS * (int)sizeof(float);
    const int IF_SMEM  = IF_SMEM_FLOATS * (int)sizeof(float);
    cudaFuncSetAttribute(mlp5_kernel, cudaFuncAttributeMaxDynamicSharedMemorySize, MLP_SMEM);
    cudaFuncSetAttribute(scanloop_kernel, cudaFuncAttributeMaxDynamicSharedMemorySize, SL_SMEM);
    cudaFuncSetAttribute(infer_kernel, cudaFuncAttributeMaxDynamicSharedMemorySize, IF_SMEM);

    float *d_sent, *d_qsum, *d_e1, *d_e2, *d_r1, *d_r2, *d_r3;
    float *d_qe1, *d_qe2, *d_qr1, *d_qr2, *d_qr3;
    cudaGetSymbolAddress((void**)&d_sent, g_sent);
    cudaGetSymbolAddress((void**)&d_qsum, g_qsum);
    cudaGetSymbolAddress((void**)&d_e1, g_e1);
    cudaGetSymbolAddress((void**)&d_e2, g_e2);
    cudaGetSymbolAddress((void**)&d_r1, g_r1);
    cudaGetSymbolAddress((void**)&d_r2, g_r2);
    cudaGetSymbolAddress((void**)&d_r3, g_r3);
    cudaGetSymbolAddress((void**)&d_qe1, g_qe1);
    cudaGetSymbolAddress((void**)&d_qe2, g_qe2);
    cudaGetSymbolAddress((void**)&d_qr1, g_qr1);
    cudaGetSymbolAddress((void**)&d_qr2, g_qr2);
    cudaGetSymbolAddress((void**)&d_qr3, g_qr3);

    embed_kernel<<<BB*SS + BB, SYM>>>(story, query, WE, PE);

    mlp5_kernel<<<dim3(BB*SS/32 + 2, 5), 128, MLP_SMEM>>>(
        d_sent, d_qsum,
        ue_W1, ue_b1, ue_W2, ue_b2, ur_W1, ur_b1, ur_W2, ur_b2,
        ie_W1, ie_b1, ie_W2, ie_b2, ir_W1, ir_b1, ir_W2, ir_b2,
        d_e1, d_e2, d_r1, d_r2, d_r3,
        d_qe1, d_qe2, d_qr1, d_qr2, d_qr3);

    gram_kernel<<<dim3(BB, 9), 128>>>();
    coef_kernel<<<dim3(BB, 9), 256>>>();
    scanloop_kernel<<<dim3(BB, 2), 256, SL_SMEM>>>();
    infer_kernel<<<BB, 128, IF_SMEM>>>(d_qe1, d_qr1, d_qr2, d_qr3, ln_g, ln_b);
    outgemm_kernel<<<dim3(VV/128, BB/16), 128>>>(Z, out);
}